// round 8
// baseline (speedup 1.0000x reference)
#include <cuda_runtime.h>
#include <cuda_bf16.h>
#include <math.h>
#include <stdint.h>

// ---------------------------------------------------------------------------
// Problem constants
// ---------------------------------------------------------------------------
#define BATCH 16
#define SEQ 256
#define NTOK (BATCH * SEQ)          // 4096
#define HID 768
#define NHEAD 12
#define HDIM 64
#define FFN 3072
#define NLAYER 6
#define NTAGS 9

// Weight scratch offsets (floats)
#define W_QKV_OFF 0
#define W_QKV_SZ  (NLAYER * HID * 3 * HID)
#define W_WO_OFF  (W_QKV_OFF + W_QKV_SZ)
#define W_WO_SZ   (NLAYER * HID * HID)
#define W_FF1_OFF (W_WO_OFF + W_WO_SZ)
#define W_FF1_SZ  (NLAYER * HID * FFN)
#define W_FF2_OFF (W_FF1_OFF + W_FF1_SZ)
#define W_FF2_SZ  (NLAYER * FFN * HID)
#define W_TOTAL   (W_FF2_OFF + W_FF2_SZ)

// ---------------------------------------------------------------------------
// Scratch (device globals; no allocation allowed)
// ---------------------------------------------------------------------------
__device__ float g_x[NTOK * HID];
__device__ float g_qkv[NTOK * 3 * HID];
__device__ float g_attn[NTOK * HID];
__device__ float g_ffn[NTOK * FFN];
__device__ float g_tmp[NTOK * HID];
__device__ float g_nmd[BATCH];
__device__ float g_w[W_TOTAL];     // tf32-rounded weights

// ---------------------------------------------------------------------------
// helpers
// ---------------------------------------------------------------------------
__device__ __forceinline__ uint32_t smem_u32(const void* p) {
    uint32_t a;
    asm("{ .reg .u64 t; cvta.to.shared.u64 t, %1; cvt.u32.u64 %0, t; }"
        : "=r"(a) : "l"(p));
    return a;
}

__device__ __forceinline__ uint32_t f2tf32(float x) {
    uint32_t r;
    asm("cvt.rna.tf32.f32 %0, %1;" : "=r"(r) : "f"(x));
    return r;
}
__device__ __forceinline__ float tf32r(float x) {
    return __uint_as_float(f2tf32(x));
}

__device__ __forceinline__ void mma_tf32_16x8x8(
    float* c, uint32_t a0, uint32_t a1, uint32_t a2, uint32_t a3,
    uint32_t b0, uint32_t b1)
{
    asm volatile(
        "mma.sync.aligned.m16n8k8.row.col.f32.tf32.tf32.f32 "
        "{%0,%1,%2,%3}, {%4,%5,%6,%7}, {%8,%9}, {%0,%1,%2,%3};"
        : "+f"(c[0]), "+f"(c[1]), "+f"(c[2]), "+f"(c[3])
        : "r"(a0), "r"(a1), "r"(a2), "r"(a3), "r"(b0), "r"(b1));
}

__device__ __forceinline__ float gelu_tanh(float v) {
    float c = 0.7978845608028654f;
    float u = c * (v + 0.044715f * v * v * v);
    return 0.5f * v * (1.0f + tanhf(u));
}

#define CP_ASYNC16(dst, src) \
    asm volatile("cp.async.cg.shared.global [%0], [%1], 16;" \
        :: "r"(dst), "l"(src) : "memory")
#define CP_COMMIT() asm volatile("cp.async.commit_group;" ::: "memory")
#define CP_WAIT2()  asm volatile("cp.async.wait_group 2;" ::: "memory")

// ---------------------------------------------------------------------------
// One-shot weight tf32 rounding: all four weight groups in one launch
// ---------------------------------------------------------------------------
__global__ __launch_bounds__(256) void conv_tf32_kernel(
    const float* __restrict__ s0, const float* __restrict__ s1,
    const float* __restrict__ s2, const float* __restrict__ s3,
    float* __restrict__ dst)
{
    int stride = gridDim.x * blockDim.x;
    int t0 = blockIdx.x * blockDim.x + threadIdx.x;
    float4* d;
    d = reinterpret_cast<float4*>(dst + W_QKV_OFF);
    for (int i = t0; i < W_QKV_SZ / 4; i += stride) {
        float4 v = reinterpret_cast<const float4*>(s0)[i];
        v.x = tf32r(v.x); v.y = tf32r(v.y); v.z = tf32r(v.z); v.w = tf32r(v.w);
        d[i] = v;
    }
    d = reinterpret_cast<float4*>(dst + W_WO_OFF);
    for (int i = t0; i < W_WO_SZ / 4; i += stride) {
        float4 v = reinterpret_cast<const float4*>(s1)[i];
        v.x = tf32r(v.x); v.y = tf32r(v.y); v.z = tf32r(v.z); v.w = tf32r(v.w);
        d[i] = v;
    }
    d = reinterpret_cast<float4*>(dst + W_FF1_OFF);
    for (int i = t0; i < W_FF1_SZ / 4; i += stride) {
        float4 v = reinterpret_cast<const float4*>(s2)[i];
        v.x = tf32r(v.x); v.y = tf32r(v.y); v.z = tf32r(v.z); v.w = tf32r(v.w);
        d[i] = v;
    }
    d = reinterpret_cast<float4*>(dst + W_FF2_OFF);
    for (int i = t0; i < W_FF2_SZ / 4; i += stride) {
        float4 v = reinterpret_cast<const float4*>(s3)[i];
        v.x = tf32r(v.x); v.y = tf32r(v.y); v.z = tf32r(v.z); v.w = tf32r(v.w);
        d[i] = v;
    }
}

// ---------------------------------------------------------------------------
// tf32 tensor-core GEMM, 3-stage cp.async pipeline.
// A: fp32 activations (cvt at fragment load). B: pre-rounded tf32 weights (raw).
// C[M,N] = A[M,K] @ B[K,N] + bias   (act=1 -> gelu). Output plain fp32.
// ---------------------------------------------------------------------------
#define AST 36
#define BST 136
#define A_STAGE (128 * AST)
#define B_STAGE (32 * BST)
#define GEMM_DSMEM ((3 * A_STAGE + 3 * B_STAGE) * 4)

__global__ __launch_bounds__(256) void gemm_tc_kernel(
    const float* __restrict__ A, const float* __restrict__ B,
    const float* __restrict__ bias, float* __restrict__ C,
    int M, int N, int K, int act)
{
    extern __shared__ float gsm[];
    float* AsB = gsm;                 // [3][128][AST]
    float* BsB = gsm + 3 * A_STAGE;   // [3][32][BST]
    const uint32_t s_as = smem_u32(AsB);
    const uint32_t s_bs = smem_u32(BsB);

    const int tid = threadIdx.x;
    const int wid = tid >> 5;
    const int lane = tid & 31;
    const int gid = lane >> 2;
    const int tig = lane & 3;
    const int moff = (wid >> 2) * 64;
    const int noff = (wid & 3) * 32;

    const int m0 = blockIdx.y * 128;
    const int n0 = blockIdx.x * 128;

    const int ar = tid >> 3, ac = (tid & 7) * 4;
    const int br = tid >> 5, bc = (tid & 31) * 4;

    float acc[4][4][4];
    #pragma unroll
    for (int i = 0; i < 4; i++)
        #pragma unroll
        for (int j = 0; j < 4; j++)
            #pragma unroll
            for (int q = 0; q < 4; q++) acc[i][j][q] = 0.f;

    const int nch = K >> 5;

    auto issue = [&](int stage, int kc) {
        #pragma unroll
        for (int i = 0; i < 4; i++) {
            int r = i * 32 + ar;
            uint32_t d = s_as + (uint32_t)(stage * A_STAGE + r * AST + ac) * 4u;
            const float* s = A + (size_t)(m0 + r) * K + kc + ac;
            CP_ASYNC16(d, s);
        }
        #pragma unroll
        for (int i = 0; i < 4; i++) {
            int r = i * 8 + br;
            uint32_t d = s_bs + (uint32_t)(stage * B_STAGE + r * BST + bc) * 4u;
            const float* s = B + (size_t)(kc + r) * N + n0 + bc;
            CP_ASYNC16(d, s);
        }
        CP_COMMIT();
    };

    issue(0, 0);
    issue(1, 32);

    #pragma unroll 1
    for (int c = 0; c < nch; c++) {
        if (c + 2 < nch) issue((c + 2) % 3, (c + 2) * 32);
        else CP_COMMIT();
        CP_WAIT2();
        __syncthreads();

        const float*    Asb = AsB + (c % 3) * A_STAGE;
        const uint32_t* Bsb = reinterpret_cast<const uint32_t*>(BsB + (c % 3) * B_STAGE);

        #pragma unroll
        for (int ks = 0; ks < 4; ks++) {
            int k0 = ks * 8;
            uint32_t a[2][4];
            #pragma unroll
            for (int mf = 0; mf < 2; mf++) {
                int r = moff + mf * 16 + gid;
                a[mf][0] = f2tf32(Asb[r * AST + k0 + tig]);
                a[mf][1] = f2tf32(Asb[(r + 8) * AST + k0 + tig]);
                a[mf][2] = f2tf32(Asb[r * AST + k0 + tig + 4]);
                a[mf][3] = f2tf32(Asb[(r + 8) * AST + k0 + tig + 4]);
            }
            uint32_t a2[2][4];
            #pragma unroll
            for (int mf = 0; mf < 2; mf++) {
                int r = moff + 32 + mf * 16 + gid;
                a2[mf][0] = f2tf32(Asb[r * AST + k0 + tig]);
                a2[mf][1] = f2tf32(Asb[(r + 8) * AST + k0 + tig]);
                a2[mf][2] = f2tf32(Asb[r * AST + k0 + tig + 4]);
                a2[mf][3] = f2tf32(Asb[(r + 8) * AST + k0 + tig + 4]);
            }
            uint32_t b[4][2];
            #pragma unroll
            for (int nf = 0; nf < 4; nf++) {
                int nc = noff + nf * 8 + gid;
                b[nf][0] = Bsb[(k0 + tig) * BST + nc];
                b[nf][1] = Bsb[(k0 + tig + 4) * BST + nc];
            }
            #pragma unroll
            for (int nf = 0; nf < 4; nf++) {
                mma_tf32_16x8x8(acc[0][nf], a[0][0], a[0][1], a[0][2], a[0][3],
                                b[nf][0], b[nf][1]);
                mma_tf32_16x8x8(acc[1][nf], a[1][0], a[1][1], a[1][2], a[1][3],
                                b[nf][0], b[nf][1]);
                mma_tf32_16x8x8(acc[2][nf], a2[0][0], a2[0][1], a2[0][2], a2[0][3],
                                b[nf][0], b[nf][1]);
                mma_tf32_16x8x8(acc[3][nf], a2[1][0], a2[1][1], a2[1][2], a2[1][3],
                                b[nf][0], b[nf][1]);
            }
        }
        __syncthreads();
    }

    // epilogue (plain fp32 outputs)
    #pragma unroll
    for (int mf = 0; mf < 4; mf++) {
        #pragma unroll
        for (int half = 0; half < 2; half++) {
            int row = m0 + moff + mf * 16 + gid + half * 8;
            float* crow = C + (size_t)row * N + n0 + noff;
            const float* brow_ = bias + n0 + noff;
            #pragma unroll
            for (int nf = 0; nf < 4; nf++) {
                int cl = nf * 8 + 2 * tig;
                float2 v;
                v.x = acc[mf][nf][half * 2 + 0] + brow_[cl];
                v.y = acc[mf][nf][half * 2 + 1] + brow_[cl + 1];
                if (act == 1) { v.x = gelu_tanh(v.x); v.y = gelu_tanh(v.y); }
                *reinterpret_cast<float2*>(crow + cl) = v;
            }
        }
    }
}

// ---------------------------------------------------------------------------
// Tensor-core flash attention (R5 numerics: cvt at staging, fp32 out)
// ---------------------------------------------------------------------------
#define KTS 264
#define VST 72
#define PST 36
#define ATN_U32 (64 * KTS + 256 * VST + 8 * 32 * PST + 256)
#define ATN_SMEM (ATN_U32 * 4)

__global__ __launch_bounds__(256) void attn_kernel(
    const float* __restrict__ qkv, const int* __restrict__ amask,
    float* __restrict__ out)
{
    extern __shared__ uint32_t ash[];
    uint32_t* Kt = ash;                    // [64][KTS]
    uint32_t* Vs = ash + 64 * KTS;         // [256][VST]
    uint32_t* Ps = Vs + 256 * VST;         // [8][32][PST]
    float* Ms = (float*)(Ps + 8 * 32 * PST);

    const int bh = blockIdx.x;
    const int b = bh / NHEAD;
    const int h = bh % NHEAD;
    const int tid = threadIdx.x;
    const int wid = tid >> 5;
    const int lane = tid & 31;
    const int gid = lane >> 2;
    const int tig = lane & 3;

    const float* base = qkv + (size_t)b * SEQ * (3 * HID);

    {
        int key = tid;
        const float* kr = base + (size_t)key * (3 * HID) + HID + h * HDIM;
        const float* vr = base + (size_t)key * (3 * HID) + 2 * HID + h * HDIM;
        #pragma unroll
        for (int d = 0; d < HDIM; d += 4) {
            float4 kv = *reinterpret_cast<const float4*>(kr + d);
            Kt[(d + 0) * KTS + key] = f2tf32(kv.x);
            Kt[(d + 1) * KTS + key] = f2tf32(kv.y);
            Kt[(d + 2) * KTS + key] = f2tf32(kv.z);
            Kt[(d + 3) * KTS + key] = f2tf32(kv.w);
            float4 vv = *reinterpret_cast<const float4*>(vr + d);
            uint4 u = make_uint4(f2tf32(vv.x), f2tf32(vv.y), f2tf32(vv.z), f2tf32(vv.w));
            *reinterpret_cast<uint4*>(&Vs[key * VST + d]) = u;
        }
        Ms[key] = (1.0f - (float)amask[b * SEQ + key]) * -1e9f;
    }

    const int qbase = wid * 32;
    uint32_t aq[2][8][4];
    #pragma unroll
    for (int mf = 0; mf < 2; mf++) {
        const float* q0 = base + (size_t)(qbase + mf * 16 + gid) * (3 * HID) + h * HDIM;
        const float* q1 = q0 + (size_t)8 * (3 * HID);
        #pragma unroll
        for (int ks = 0; ks < 8; ks++) {
            aq[mf][ks][0] = f2tf32(q0[ks * 8 + tig] * 0.125f);
            aq[mf][ks][1] = f2tf32(q1[ks * 8 + tig] * 0.125f);
            aq[mf][ks][2] = f2tf32(q0[ks * 8 + tig + 4] * 0.125f);
            aq[mf][ks][3] = f2tf32(q1[ks * 8 + tig + 4] * 0.125f);
        }
    }
    __syncthreads();

    float mrun[4] = {-1e30f, -1e30f, -1e30f, -1e30f};
    float lrun[4] = {0.f, 0.f, 0.f, 0.f};
    float O[2][8][4];
    #pragma unroll
    for (int i = 0; i < 2; i++)
        #pragma unroll
        for (int j = 0; j < 8; j++)
            #pragma unroll
            for (int q = 0; q < 4; q++) O[i][j][q] = 0.f;

    uint32_t* Pw = Ps + wid * 32 * PST;

    #pragma unroll 1
    for (int kc = 0; kc < 8; kc++) {
        const int kb = kc * 32;

        float sacc[2][4][4];
        #pragma unroll
        for (int i = 0; i < 2; i++)
            #pragma unroll
            for (int j = 0; j < 4; j++)
                #pragma unroll
                for (int q = 0; q < 4; q++) sacc[i][j][q] = 0.f;

        #pragma unroll
        for (int ks = 0; ks < 8; ks++) {
            int k0 = ks * 8;
            uint32_t bk[4][2];
            #pragma unroll
            for (int nf = 0; nf < 4; nf++) {
                bk[nf][0] = Kt[(k0 + tig) * KTS + kb + nf * 8 + gid];
                bk[nf][1] = Kt[(k0 + tig + 4) * KTS + kb + nf * 8 + gid];
            }
            #pragma unroll
            for (int mf = 0; mf < 2; mf++)
                #pragma unroll
                for (int nf = 0; nf < 4; nf++)
                    mma_tf32_16x8x8(sacc[mf][nf],
                        aq[mf][ks][0], aq[mf][ks][1], aq[mf][ks][2], aq[mf][ks][3],
                        bk[nf][0], bk[nf][1]);
        }

        #pragma unroll
        for (int nf = 0; nf < 4; nf++) {
            float mb0 = Ms[kb + nf * 8 + 2 * tig];
            float mb1 = Ms[kb + nf * 8 + 2 * tig + 1];
            #pragma unroll
            for (int mf = 0; mf < 2; mf++) {
                sacc[mf][nf][0] += mb0; sacc[mf][nf][1] += mb1;
                sacc[mf][nf][2] += mb0; sacc[mf][nf][3] += mb1;
            }
        }

        #pragma unroll
        for (int rs = 0; rs < 4; rs++) {
            int mf = rs >> 1, cp = rs & 1;
            float lmax = -1e30f;
            #pragma unroll
            for (int nf = 0; nf < 4; nf++)
                lmax = fmaxf(lmax, fmaxf(sacc[mf][nf][2 * cp], sacc[mf][nf][2 * cp + 1]));
            lmax = fmaxf(lmax, __shfl_xor_sync(0xffffffffu, lmax, 1));
            lmax = fmaxf(lmax, __shfl_xor_sync(0xffffffffu, lmax, 2));
            float mnew = fmaxf(mrun[rs], lmax);
            float corr = __expf(mrun[rs] - mnew);
            float psum = 0.f;
            int prow = mf * 16 + gid + cp * 8;
            #pragma unroll
            for (int nf = 0; nf < 4; nf++) {
                uint32_t u0 = f2tf32(__expf(sacc[mf][nf][2 * cp] - mnew));
                uint32_t u1 = f2tf32(__expf(sacc[mf][nf][2 * cp + 1] - mnew));
                psum += __uint_as_float(u0) + __uint_as_float(u1);
                Pw[prow * PST + nf * 8 + 2 * tig] = u0;
                Pw[prow * PST + nf * 8 + 2 * tig + 1] = u1;
            }
            psum += __shfl_xor_sync(0xffffffffu, psum, 1);
            psum += __shfl_xor_sync(0xffffffffu, psum, 2);
            lrun[rs] = lrun[rs] * corr + psum;
            mrun[rs] = mnew;
            #pragma unroll
            for (int nf2 = 0; nf2 < 8; nf2++) {
                O[mf][nf2][2 * cp] *= corr;
                O[mf][nf2][2 * cp + 1] *= corr;
            }
        }
        __syncwarp();

        #pragma unroll
        for (int ks2 = 0; ks2 < 4; ks2++) {
            int k0 = ks2 * 8;
            uint32_t ap[2][4];
            #pragma unroll
            for (int mf = 0; mf < 2; mf++) {
                int r = mf * 16 + gid;
                ap[mf][0] = Pw[r * PST + k0 + tig];
                ap[mf][1] = Pw[(r + 8) * PST + k0 + tig];
                ap[mf][2] = Pw[r * PST + k0 + tig + 4];
                ap[mf][3] = Pw[(r + 8) * PST + k0 + tig + 4];
            }
            #pragma unroll
            for (int nf2 = 0; nf2 < 8; nf2++) {
                uint32_t bv0 = Vs[(kb + k0 + tig) * VST + nf2 * 8 + gid];
                uint32_t bv1 = Vs[(kb + k0 + tig + 4) * VST + nf2 * 8 + gid];
                mma_tf32_16x8x8(O[0][nf2], ap[0][0], ap[0][1], ap[0][2], ap[0][3],
                                bv0, bv1);
                mma_tf32_16x8x8(O[1][nf2], ap[1][0], ap[1][1], ap[1][2], ap[1][3],
                                bv0, bv1);
            }
        }
        __syncwarp();
    }

    float inv[4];
    #pragma unroll
    for (int rs = 0; rs < 4; rs++) inv[rs] = 1.0f / lrun[rs];
    #pragma unroll
    for (int mf = 0; mf < 2; mf++) {
        #pragma unroll
        for (int cp = 0; cp < 2; cp++) {
            int row = b * SEQ + qbase + mf * 16 + gid + cp * 8;
            float* orow = out + (size_t)row * HID + h * HDIM;
            float iv = inv[mf * 2 + cp];
            #pragma unroll
            for (int nf2 = 0; nf2 < 8; nf2++) {
                float2 v;
                v.x = O[mf][nf2][2 * cp] * iv;
                v.y = O[mf][nf2][2 * cp + 1] * iv;
                *reinterpret_cast<float2*>(orow + nf2 * 8 + 2 * tig) = v;
            }
        }
    }
}

// ---------------------------------------------------------------------------
// Warp-per-row LayerNorms (plain fp32 outputs)
// ---------------------------------------------------------------------------
__device__ __forceinline__ void warp_ln_write(
    float* dst, const float* v, const float* lns, const float* lnb,
    int lane, float mean, float inv)
{
    #pragma unroll
    for (int i = 0; i < 6; i++) {
        int c = i * 128 + lane * 4;
        float4 g = *reinterpret_cast<const float4*>(lns + c);
        float4 bq = *reinterpret_cast<const float4*>(lnb + c);
        float4 o;
        o.x = (v[i * 4 + 0] - mean) * inv * g.x + bq.x;
        o.y = (v[i * 4 + 1] - mean) * inv * g.y + bq.y;
        o.z = (v[i * 4 + 2] - mean) * inv * g.z + bq.z;
        o.w = (v[i * 4 + 3] - mean) * inv * g.w + bq.w;
        *reinterpret_cast<float4*>(dst + c) = o;
    }
}

__device__ __forceinline__ void warp_ln_stats(const float* v, float& mean, float& inv)
{
    float s = 0.f, sq = 0.f;
    #pragma unroll
    for (int j = 0; j < 24; j++) { s += v[j]; sq += v[j] * v[j]; }
    #pragma unroll
    for (int o = 16; o > 0; o >>= 1) {
        s  += __shfl_xor_sync(0xffffffffu, s, o);
        sq += __shfl_xor_sync(0xffffffffu, sq, o);
    }
    mean = s * (1.0f / HID);
    float var = sq * (1.0f / HID) - mean * mean;
    inv = rsqrtf(var + 1e-12f);
}

__global__ __launch_bounds__(256) void embed_ln_kernel(
    const int* __restrict__ ids, const float* __restrict__ wemb,
    const float* __restrict__ pemb, const float* __restrict__ lns,
    const float* __restrict__ lnb, float* __restrict__ xout)
{
    int wid = threadIdx.x >> 5, lane = threadIdx.x & 31;
    int row = blockIdx.x * 8 + wid;
    int spos = row & (SEQ - 1);
    int id = ids[row];
    const float* wr = wemb + (size_t)id * HID;
    const float* pr = pemb + (size_t)spos * HID;
    float v[24];
    #pragma unroll
    for (int i = 0; i < 6; i++) {
        int c = i * 128 + lane * 4;
        float4 a = *reinterpret_cast<const float4*>(wr + c);
        float4 p = *reinterpret_cast<const float4*>(pr + c);
        v[i * 4 + 0] = a.x + p.x; v[i * 4 + 1] = a.y + p.y;
        v[i * 4 + 2] = a.z + p.z; v[i * 4 + 3] = a.w + p.w;
    }
    float mean, inv;
    warp_ln_stats(v, mean, inv);
    warp_ln_write(xout + (size_t)row * HID, v, lns, lnb, lane, mean, inv);
}

__global__ __launch_bounds__(256) void resid_ln_kernel(
    float* __restrict__ x, const float* __restrict__ y,
    const float* __restrict__ lns, const float* __restrict__ lnb)
{
    int wid = threadIdx.x >> 5, lane = threadIdx.x & 31;
    int row = blockIdx.x * 8 + wid;
    float* xr = x + (size_t)row * HID;
    const float* yr = y + (size_t)row * HID;
    float v[24];
    #pragma unroll
    for (int i = 0; i < 6; i++) {
        int c = i * 128 + lane * 4;
        float4 a = *reinterpret_cast<const float4*>(xr + c);
        float4 bq = *reinterpret_cast<const float4*>(yr + c);
        v[i * 4 + 0] = a.x + bq.x; v[i * 4 + 1] = a.y + bq.y;
        v[i * 4 + 2] = a.z + bq.z; v[i * 4 + 3] = a.w + bq.w;
    }
    float mean, inv;
    warp_ln_stats(v, mean, inv);
    warp_ln_write(xr, v, lns, lnb, lane, mean, inv);
}

// ---------------------------------------------------------------------------
// Classifier: warp per row (fp32 exact)
// ---------------------------------------------------------------------------
__global__ __launch_bounds__(256) void cls_kernel(
    const float* __restrict__ x, const float* __restrict__ W,
    const float* __restrict__ bias, float* __restrict__ out)
{
    int wid = threadIdx.x >> 5, lane = threadIdx.x & 31;
    int row = blockIdx.x * 8 + wid;
    const float* xr = x + (size_t)row * HID;
    float acc[NTAGS];
    #pragma unroll
    for (int n = 0; n < NTAGS; n++) acc[n] = 0.f;
    #pragma unroll
    for (int i = 0; i < 24; i++) {
        int k = i * 32 + lane;
        float xv = xr[k];
        const float* wr = W + k * NTAGS;
        #pragma unroll
        for (int n = 0; n < NTAGS; n++) acc[n] += xv * wr[n];
    }
    #pragma unroll
    for (int n = 0; n < NTAGS; n++) {
        #pragma unroll
        for (int o = 16; o > 0; o >>= 1)
            acc[n] += __shfl_xor_sync(0xffffffffu, acc[n], o);
    }
    if (lane < NTAGS)
        out[(size_t)row * NTAGS + lane] = acc[lane] + bias[lane];
}

// ---------------------------------------------------------------------------
// CRF: one warp per batch element
// ---------------------------------------------------------------------------
__global__ __launch_bounds__(32) void crf_kernel(
    const float* __restrict__ logits, const int* __restrict__ labels,
    const float* __restrict__ cstart, const float* __restrict__ cend,
    const float* __restrict__ ctrans, float* __restrict__ nmd)
{
    int b = blockIdx.x;
    int lane = threadIdx.x;
    const float* lg = logits + (size_t)b * SEQ * NTAGS;
    const int* lab = labels + b * SEQ;

    float part = 0.f;
    int cnt = 0;
    for (int s = lane; s < SEQ; s += 32) {
        int lv = lab[s];
        bool mk = (s == 0) || (lv != -100);
        cnt += mk ? 1 : 0;
        if (s >= 1 && mk) {
            int lp = lab[s - 1]; int tp = (lp == -100) ? 0 : lp;
            int tc = (lv == -100) ? 0 : lv;
            part += ctrans[tp * NTAGS + tc] + lg[s * NTAGS + tc];
        }
    }
    #pragma unroll
    for (int o = 16; o > 0; o >>= 1) {
        part += __shfl_xor_sync(0xffffffffu, part, o);
        cnt  += __shfl_xor_sync(0xffffffffu, cnt, o);
    }

    int t = (lane < NTAGS) ? lane : 0;
    float tt[NTAGS];
    #pragma unroll
    for (int i = 0; i < NTAGS; i++) tt[i] = ctrans[i * NTAGS + t];
    float score = cstart[t] + lg[t];

    for (int s = 1; s < SEQ; s++) {
        float e = lg[s * NTAGS + t];
        float v[NTAGS];
        float vmax = -1e30f;
        #pragma unroll
        for (int i = 0; i < NTAGS; i++) {
            float si = __shfl_sync(0xffffffffu, score, i);
            v[i] = si + tt[i];
            vmax = fmaxf(vmax, v[i]);
        }
        float smv = 0.f;
        #pragma unroll
        for (int i = 0; i < NTAGS; i++) smv += __expf(v[i] - vmax);
        float nxt = vmax + __logf(smv) + e;
        bool mk = (lab[s] != -100);
        score = mk ? nxt : score;
    }

    float fin = score + cend[t];
    float gmax = -1e30f;
    #pragma unroll
    for (int i = 0; i < NTAGS; i++)
        gmax = fmaxf(gmax, __shfl_sync(0xffffffffu, fin, i));
    float gs = 0.f;
    #pragma unroll
    for (int i = 0; i < NTAGS; i++)
        gs += __expf(__shfl_sync(0xffffffffu, fin, i) - gmax);
    float denom = gmax + __logf(gs);

    if (lane == 0) {
        int l0 = lab[0]; int t0 = (l0 == -100) ? 0 : l0;
        int seq_end = cnt - 1;
        int le = lab[seq_end]; int te = (le == -100) ? 0 : le;
        float num = part + cstart[t0] + lg[t0] + cend[te];
        nmd[b] = num - denom;
    }
}

__global__ __launch_bounds__(32) void loss_kernel(
    const float* __restrict__ nmd, float* __restrict__ out)
{
    int lane = threadIdx.x;
    float v = (lane < BATCH) ? nmd[lane] : 0.f;
    #pragma unroll
    for (int o = 16; o > 0; o >>= 1) v += __shfl_xor_sync(0xffffffffu, v, o);
    if (lane == 0) out[0] = -(v * (1.0f / BATCH));
}

// ---------------------------------------------------------------------------
// Launcher
// ---------------------------------------------------------------------------
extern "C" void kernel_launch(void* const* d_in, const int* in_sizes, int n_in,
                              void* d_out, int out_size)
{
    const int*   input_ids = (const int*)d_in[0];
    const int*   amask     = (const int*)d_in[1];
    const int*   labels    = (const int*)d_in[2];
    const float* word_emb  = (const float*)d_in[3];
    const float* pos_emb   = (const float*)d_in[4];
    const float* eln_s     = (const float*)d_in[5];
    const float* eln_b     = (const float*)d_in[6];
    const float* Wqkv      = (const float*)d_in[7];
    const float* bqkv      = (const float*)d_in[8];
    const float* Wo        = (const float*)d_in[9];
    const float* bo        = (const float*)d_in[10];
    const float* ln1s      = (const float*)d_in[11];
    const float* ln1b      = (const float*)d_in[12];
    const float* Wff1      = (const float*)d_in[13];
    const float* bff1      = (const float*)d_in[14];
    const float* Wff2      = (const float*)d_in[15];
    const float* bff2      = (const float*)d_in[16];
    const float* ln2s      = (const float*)d_in[17];
    const float* ln2b      = (const float*)d_in[18];
    const float* Wcls      = (const float*)d_in[19];
    const float* bcls      = (const float*)d_in[20];
    const float* cstart    = (const float*)d_in[21];
    const float* cend      = (const float*)d_in[22];
    const float* ctrans    = (const float*)d_in[23];
    float* out = (float*)d_out;

    float *x, *qkv, *attn, *ffn, *tmp, *nmd, *w;
    cudaGetSymbolAddress((void**)&x,    g_x);
    cudaGetSymbolAddress((void**)&qkv,  g_qkv);
    cudaGetSymbolAddress((void**)&attn, g_attn);
    cudaGetSymbolAddress((void**)&ffn,  g_ffn);
    cudaGetSymbolAddress((void**)&tmp,  g_tmp);
    cudaGetSymbolAddress((void**)&nmd,  g_nmd);
    cudaGetSymbolAddress((void**)&w,    g_w);

    cudaFuncSetAttribute(gemm_tc_kernel,
        cudaFuncAttributeMaxDynamicSharedMemorySize, GEMM_DSMEM);
    cudaFuncSetAttribute(attn_kernel,
        cudaFuncAttributeMaxDynamicSharedMemorySize, ATN_SMEM);

    // Uniform max-shared carveout on EVERY kernel to eliminate per-launch
    // L1/shared carveout reconfiguration stalls across the graph.
    cudaFuncSetAttribute(gemm_tc_kernel,
        cudaFuncAttributePreferredSharedMemoryCarveout, 100);
    cudaFuncSetAttribute(attn_kernel,
        cudaFuncAttributePreferredSharedMemoryCarveout, 100);
    cudaFuncSetAttribute(conv_tf32_kernel,
        cudaFuncAttributePreferredSharedMemoryCarveout, 100);
    cudaFuncSetAttribute(embed_ln_kernel,
        cudaFuncAttributePreferredSharedMemoryCarveout, 100);
    cudaFuncSetAttribute(resid_ln_kernel,
        cudaFuncAttributePreferredSharedMemoryCarveout, 100);
    cudaFuncSetAttribute(cls_kernel,
        cudaFuncAttributePreferredSharedMemoryCarveout, 100);
    cudaFuncSetAttribute(crf_kernel,
        cudaFuncAttributePreferredSharedMemoryCarveout, 100);
    cudaFuncSetAttribute(loss_kernel,
        cudaFuncAttributePreferredSharedMemoryCarveout, 100);

    conv_tf32_kernel<<<1184, 256>>>(Wqkv, Wo, Wff1, Wff2, w);

    embed_ln_kernel<<<NTOK / 8, 256>>>(input_ids, word_emb, pos_emb, eln_s, eln_b, x);

    for (int L = 0; L < NLAYER; L++) {
        gemm_tc_kernel<<<dim3(3 * HID / 128, NTOK / 128), 256, GEMM_DSMEM>>>(
            x, w + W_QKV_OFF + (size_t)L * HID * 3 * HID,
            bqkv + (size_t)L * 3 * HID, qkv, NTOK, 3 * HID, HID, 0);

        attn_kernel<<<BATCH * NHEAD, 256, ATN_SMEM>>>(qkv, amask, attn);

        gemm_tc_kernel<<<dim3(HID / 128, NTOK / 128), 256, GEMM_DSMEM>>>(
            attn, w + W_WO_OFF + (size_t)L * HID * HID,
            bo + (size_t)L * HID, tmp, NTOK, HID, HID, 0);

        resid_ln_kernel<<<NTOK / 8, 256>>>(x, tmp,
            ln1s + (size_t)L * HID, ln1b + (size_t)L * HID);

        gemm_tc_kernel<<<dim3(FFN / 128, NTOK / 128), 256, GEMM_DSMEM>>>(
            x, w + W_FF1_OFF + (size_t)L * HID * FFN,
            bff1 + (size_t)L * FFN, ffn, NTOK, FFN, HID, 1);

        gemm_tc_kernel<<<dim3(HID / 128, NTOK / 128), 256, GEMM_DSMEM>>>(
            ffn, w + W_FF2_OFF + (size_t)L * FFN * HID,
            bff2 + (size_t)L * HID, tmp, NTOK, HID, FFN, 0);

        resid_ln_kernel<<<NTOK / 8, 256>>>(x, tmp,
            ln2s + (size_t)L * HID, ln2b + (size_t)L * HID);
    }

    cls_kernel<<<NTOK / 8, 256>>>(x, Wcls, bcls, out + 1);
    crf_kernel<<<BATCH, 32>>>(out + 1, labels, cstart, cend, ctrans, nmd);
    loss_kernel<<<1, 32>>>(nmd, out);
}

// round 9
// speedup vs baseline: 1.0998x; 1.0998x over previous
#include <cuda_runtime.h>
#include <cuda_bf16.h>
#include <math.h>
#include <stdint.h>

// ---------------------------------------------------------------------------
// Problem constants
// ---------------------------------------------------------------------------
#define BATCH 16
#define SEQ 256
#define NTOK (BATCH * SEQ)          // 4096
#define HID 768
#define NHEAD 12
#define HDIM 64
#define FFN 3072
#define NLAYER 6
#define NTAGS 9

// Weight scratch offsets (floats)
#define W_QKV_OFF 0
#define W_QKV_SZ  (NLAYER * HID * 3 * HID)
#define W_WO_OFF  (W_QKV_OFF + W_QKV_SZ)
#define W_WO_SZ   (NLAYER * HID * HID)
#define W_FF1_OFF (W_WO_OFF + W_WO_SZ)
#define W_FF1_SZ  (NLAYER * HID * FFN)
#define W_FF2_OFF (W_FF1_OFF + W_FF1_SZ)
#define W_FF2_SZ  (NLAYER * FFN * HID)
#define W_TOTAL   (W_FF2_OFF + W_FF2_SZ)

// ---------------------------------------------------------------------------
// Scratch (device globals; no allocation allowed)
// ---------------------------------------------------------------------------
__device__ float g_x[NTOK * HID];       // residual stream (fp32, exact)
__device__ float g_xr[NTOK * HID];      // tf32-rounded copy of x (GEMM A input)
__device__ float g_qkv[NTOK * 3 * HID]; // rounded (QKV epilogue)
__device__ float g_attn[NTOK * HID];    // rounded (attn epilogue)
__device__ float g_ffn[NTOK * FFN];     // rounded (FF1 epilogue)
__device__ float g_tmp[NTOK * HID];     // fp32 (WO / FF2 outputs, feed LN)
__device__ float g_nmd[BATCH];
__device__ float g_w[W_TOTAL];          // tf32-rounded weights

// ---------------------------------------------------------------------------
// helpers
// ---------------------------------------------------------------------------
__device__ __forceinline__ uint32_t smem_u32(const void* p) {
    uint32_t a;
    asm("{ .reg .u64 t; cvta.to.shared.u64 t, %1; cvt.u32.u64 %0, t; }"
        : "=r"(a) : "l"(p));
    return a;
}

__device__ __forceinline__ uint32_t f2tf32(float x) {
    uint32_t r;
    asm("cvt.rna.tf32.f32 %0, %1;" : "=r"(r) : "f"(x));
    return r;
}
__device__ __forceinline__ float tf32r(float x) {
    return __uint_as_float(f2tf32(x));
}

__device__ __forceinline__ void mma_tf32_16x8x8(
    float* c, uint32_t a0, uint32_t a1, uint32_t a2, uint32_t a3,
    uint32_t b0, uint32_t b1)
{
    asm volatile(
        "mma.sync.aligned.m16n8k8.row.col.f32.tf32.tf32.f32 "
        "{%0,%1,%2,%3}, {%4,%5,%6,%7}, {%8,%9}, {%0,%1,%2,%3};"
        : "+f"(c[0]), "+f"(c[1]), "+f"(c[2]), "+f"(c[3])
        : "r"(a0), "r"(a1), "r"(a2), "r"(a3), "r"(b0), "r"(b1));
}

__device__ __forceinline__ float gelu_tanh(float v) {
    float c = 0.7978845608028654f;
    float u = c * (v + 0.044715f * v * v * v);
    return 0.5f * v * (1.0f + tanhf(u));
}

#define CP_ASYNC16(dst, src) \
    asm volatile("cp.async.cg.shared.global [%0], [%1], 16;" \
        :: "r"(dst), "l"(src) : "memory")
#define CP_COMMIT() asm volatile("cp.async.commit_group;" ::: "memory")
#define CP_WAIT2()  asm volatile("cp.async.wait_group 2;" ::: "memory")

// ---------------------------------------------------------------------------
// One-shot weight tf32 rounding: all four weight groups in one launch
// ---------------------------------------------------------------------------
__global__ __launch_bounds__(256) void conv_tf32_kernel(
    const float* __restrict__ s0, const float* __restrict__ s1,
    const float* __restrict__ s2, const float* __restrict__ s3,
    float* __restrict__ dst)
{
    int stride = gridDim.x * blockDim.x;
    int t0 = blockIdx.x * blockDim.x + threadIdx.x;
    float4* d;
    d = reinterpret_cast<float4*>(dst + W_QKV_OFF);
    for (int i = t0; i < W_QKV_SZ / 4; i += stride) {
        float4 v = reinterpret_cast<const float4*>(s0)[i];
        v.x = tf32r(v.x); v.y = tf32r(v.y); v.z = tf32r(v.z); v.w = tf32r(v.w);
        d[i] = v;
    }
    d = reinterpret_cast<float4*>(dst + W_WO_OFF);
    for (int i = t0; i < W_WO_SZ / 4; i += stride) {
        float4 v = reinterpret_cast<const float4*>(s1)[i];
        v.x = tf32r(v.x); v.y = tf32r(v.y); v.z = tf32r(v.z); v.w = tf32r(v.w);
        d[i] = v;
    }
    d = reinterpret_cast<float4*>(dst + W_FF1_OFF);
    for (int i = t0; i < W_FF1_SZ / 4; i += stride) {
        float4 v = reinterpret_cast<const float4*>(s2)[i];
        v.x = tf32r(v.x); v.y = tf32r(v.y); v.z = tf32r(v.z); v.w = tf32r(v.w);
        d[i] = v;
    }
    d = reinterpret_cast<float4*>(dst + W_FF2_OFF);
    for (int i = t0; i < W_FF2_SZ / 4; i += stride) {
        float4 v = reinterpret_cast<const float4*>(s3)[i];
        v.x = tf32r(v.x); v.y = tf32r(v.y); v.z = tf32r(v.z); v.w = tf32r(v.w);
        d[i] = v;
    }
}

// ---------------------------------------------------------------------------
// tf32 tensor-core GEMM, 3-stage cp.async, 2 CTAs/SM, zero cvt in hot loop.
// A and B must be tf32-representable fp32 (raw-bit feed).
// act bit0 = gelu, bit1 = round output to tf32.
// ---------------------------------------------------------------------------
#define AST 36
#define BST 136
#define A_STAGE (128 * AST)
#define B_STAGE (32 * BST)
#define GEMM_DSMEM ((3 * A_STAGE + 3 * B_STAGE) * 4)

__global__ __launch_bounds__(256, 2) void gemm_tc_kernel(
    const float* __restrict__ A, const float* __restrict__ B,
    const float* __restrict__ bias, float* __restrict__ C,
    int M, int N, int K, int act)
{
    extern __shared__ float gsm[];
    float* AsB = gsm;                 // [3][128][AST]
    float* BsB = gsm + 3 * A_STAGE;   // [3][32][BST]
    const uint32_t s_as = smem_u32(AsB);
    const uint32_t s_bs = smem_u32(BsB);

    const int tid = threadIdx.x;
    const int wid = tid >> 5;
    const int lane = tid & 31;
    const int gid = lane >> 2;
    const int tig = lane & 3;
    const int moff = (wid >> 2) * 64;
    const int noff = (wid & 3) * 32;

    const int m0 = blockIdx.y * 128;
    const int n0 = blockIdx.x * 128;

    const int ar = tid >> 3, ac = (tid & 7) * 4;
    const int br = tid >> 5, bc = (tid & 31) * 4;

    float acc[4][4][4];
    #pragma unroll
    for (int i = 0; i < 4; i++)
        #pragma unroll
        for (int j = 0; j < 4; j++)
            #pragma unroll
            for (int q = 0; q < 4; q++) acc[i][j][q] = 0.f;

    const int nch = K >> 5;

    auto issue = [&](int stage, int kc) {
        #pragma unroll
        for (int i = 0; i < 4; i++) {
            int r = i * 32 + ar;
            uint32_t d = s_as + (uint32_t)(stage * A_STAGE + r * AST + ac) * 4u;
            const float* s = A + (size_t)(m0 + r) * K + kc + ac;
            CP_ASYNC16(d, s);
        }
        #pragma unroll
        for (int i = 0; i < 4; i++) {
            int r = i * 8 + br;
            uint32_t d = s_bs + (uint32_t)(stage * B_STAGE + r * BST + bc) * 4u;
            const float* s = B + (size_t)(kc + r) * N + n0 + bc;
            CP_ASYNC16(d, s);
        }
        CP_COMMIT();
    };

    issue(0, 0);
    issue(1, 32);

    #pragma unroll 1
    for (int c = 0; c < nch; c++) {
        if (c + 2 < nch) issue((c + 2) % 3, (c + 2) * 32);
        else CP_COMMIT();
        CP_WAIT2();
        __syncthreads();

        const uint32_t* Asb = reinterpret_cast<const uint32_t*>(AsB + (c % 3) * A_STAGE);
        const uint32_t* Bsb = reinterpret_cast<const uint32_t*>(BsB + (c % 3) * B_STAGE);

        #pragma unroll
        for (int ks = 0; ks < 4; ks++) {
            int k0 = ks * 8;
            uint32_t a[2][4];
            #pragma unroll
            for (int mf = 0; mf < 2; mf++) {
                int r = moff + mf * 16 + gid;
                a[mf][0] = Asb[r * AST + k0 + tig];
                a[mf][1] = Asb[(r + 8) * AST + k0 + tig];
                a[mf][2] = Asb[r * AST + k0 + tig + 4];
                a[mf][3] = Asb[(r + 8) * AST + k0 + tig + 4];
            }
            uint32_t a2[2][4];
            #pragma unroll
            for (int mf = 0; mf < 2; mf++) {
                int r = moff + 32 + mf * 16 + gid;
                a2[mf][0] = Asb[r * AST + k0 + tig];
                a2[mf][1] = Asb[(r + 8) * AST + k0 + tig];
                a2[mf][2] = Asb[r * AST + k0 + tig + 4];
                a2[mf][3] = Asb[(r + 8) * AST + k0 + tig + 4];
            }
            uint32_t b[4][2];
            #pragma unroll
            for (int nf = 0; nf < 4; nf++) {
                int nc = noff + nf * 8 + gid;
                b[nf][0] = Bsb[(k0 + tig) * BST + nc];
                b[nf][1] = Bsb[(k0 + tig + 4) * BST + nc];
            }
            #pragma unroll
            for (int nf = 0; nf < 4; nf++) {
                mma_tf32_16x8x8(acc[0][nf], a[0][0], a[0][1], a[0][2], a[0][3],
                                b[nf][0], b[nf][1]);
                mma_tf32_16x8x8(acc[1][nf], a[1][0], a[1][1], a[1][2], a[1][3],
                                b[nf][0], b[nf][1]);
                mma_tf32_16x8x8(acc[2][nf], a2[0][0], a2[0][1], a2[0][2], a2[0][3],
                                b[nf][0], b[nf][1]);
                mma_tf32_16x8x8(acc[3][nf], a2[1][0], a2[1][1], a2[1][2], a2[1][3],
                                b[nf][0], b[nf][1]);
            }
        }
        __syncthreads();
    }

    // epilogue
    #pragma unroll
    for (int mf = 0; mf < 4; mf++) {
        #pragma unroll
        for (int half = 0; half < 2; half++) {
            int row = m0 + moff + mf * 16 + gid + half * 8;
            float* crow = C + (size_t)row * N + n0 + noff;
            const float* brow_ = bias + n0 + noff;
            #pragma unroll
            for (int nf = 0; nf < 4; nf++) {
                int cl = nf * 8 + 2 * tig;
                float vx = acc[mf][nf][half * 2 + 0] + brow_[cl];
                float vy = acc[mf][nf][half * 2 + 1] + brow_[cl + 1];
                if (act & 1) { vx = gelu_tanh(vx); vy = gelu_tanh(vy); }
                float2 v;
                if (act & 2) { v.x = tf32r(vx); v.y = tf32r(vy); }
                else         { v.x = vx;        v.y = vy; }
                *reinterpret_cast<float2*>(crow + cl) = v;
            }
        }
    }
}

// ---------------------------------------------------------------------------
// Tensor-core flash attention. qkv pre-rounded -> raw-bit staging (zero cvt).
// Output rounded to tf32 (feeds WO GEMM A). Numerics identical to R5.
// ---------------------------------------------------------------------------
#define KTS 264
#define VST 72
#define PST 36
#define ATN_U32 (64 * KTS + 256 * VST + 8 * 32 * PST + 256)
#define ATN_SMEM (ATN_U32 * 4)

__global__ __launch_bounds__(256) void attn_kernel(
    const float* __restrict__ qkv, const int* __restrict__ amask,
    float* __restrict__ out)
{
    extern __shared__ uint32_t ash[];
    uint32_t* Kt = ash;                    // [64][KTS]
    uint32_t* Vs = ash + 64 * KTS;         // [256][VST]
    uint32_t* Ps = Vs + 256 * VST;         // [8][32][PST]
    float* Ms = (float*)(Ps + 8 * 32 * PST);

    const int bh = blockIdx.x;
    const int b = bh / NHEAD;
    const int h = bh % NHEAD;
    const int tid = threadIdx.x;
    const int wid = tid >> 5;
    const int lane = tid & 31;
    const int gid = lane >> 2;
    const int tig = lane & 3;

    const float* base = qkv + (size_t)b * SEQ * (3 * HID);

    {
        int key = tid;
        const uint32_t* kr = reinterpret_cast<const uint32_t*>(
            base + (size_t)key * (3 * HID) + HID + h * HDIM);
        const uint32_t* vr = reinterpret_cast<const uint32_t*>(
            base + (size_t)key * (3 * HID) + 2 * HID + h * HDIM);
        #pragma unroll
        for (int d = 0; d < HDIM; d += 4) {
            uint4 kv = *reinterpret_cast<const uint4*>(kr + d);
            Kt[(d + 0) * KTS + key] = kv.x;
            Kt[(d + 1) * KTS + key] = kv.y;
            Kt[(d + 2) * KTS + key] = kv.z;
            Kt[(d + 3) * KTS + key] = kv.w;
            *reinterpret_cast<uint4*>(&Vs[key * VST + d]) =
                *reinterpret_cast<const uint4*>(vr + d);
        }
        Ms[key] = (1.0f - (float)amask[b * SEQ + key]) * -1e9f;
    }

    // resident Q fragments, *0.125 (exact; qkv already tf32-rounded)
    const int qbase = wid * 32;
    uint32_t aq[2][8][4];
    #pragma unroll
    for (int mf = 0; mf < 2; mf++) {
        const float* q0 = base + (size_t)(qbase + mf * 16 + gid) * (3 * HID) + h * HDIM;
        const float* q1 = q0 + (size_t)8 * (3 * HID);
        #pragma unroll
        for (int ks = 0; ks < 8; ks++) {
            aq[mf][ks][0] = __float_as_uint(q0[ks * 8 + tig] * 0.125f);
            aq[mf][ks][1] = __float_as_uint(q1[ks * 8 + tig] * 0.125f);
            aq[mf][ks][2] = __float_as_uint(q0[ks * 8 + tig + 4] * 0.125f);
            aq[mf][ks][3] = __float_as_uint(q1[ks * 8 + tig + 4] * 0.125f);
        }
    }
    __syncthreads();

    float mrun[4] = {-1e30f, -1e30f, -1e30f, -1e30f};
    float lrun[4] = {0.f, 0.f, 0.f, 0.f};
    float O[2][8][4];
    #pragma unroll
    for (int i = 0; i < 2; i++)
        #pragma unroll
        for (int j = 0; j < 8; j++)
            #pragma unroll
            for (int q = 0; q < 4; q++) O[i][j][q] = 0.f;

    uint32_t* Pw = Ps + wid * 32 * PST;

    #pragma unroll 1
    for (int kc = 0; kc < 8; kc++) {
        const int kb = kc * 32;

        float sacc[2][4][4];
        #pragma unroll
        for (int i = 0; i < 2; i++)
            #pragma unroll
            for (int j = 0; j < 4; j++)
                #pragma unroll
                for (int q = 0; q < 4; q++) sacc[i][j][q] = 0.f;

        #pragma unroll
        for (int ks = 0; ks < 8; ks++) {
            int k0 = ks * 8;
            uint32_t bk[4][2];
            #pragma unroll
            for (int nf = 0; nf < 4; nf++) {
                bk[nf][0] = Kt[(k0 + tig) * KTS + kb + nf * 8 + gid];
                bk[nf][1] = Kt[(k0 + tig + 4) * KTS + kb + nf * 8 + gid];
            }
            #pragma unroll
            for (int mf = 0; mf < 2; mf++)
                #pragma unroll
                for (int nf = 0; nf < 4; nf++)
                    mma_tf32_16x8x8(sacc[mf][nf],
                        aq[mf][ks][0], aq[mf][ks][1], aq[mf][ks][2], aq[mf][ks][3],
                        bk[nf][0], bk[nf][1]);
        }

        #pragma unroll
        for (int nf = 0; nf < 4; nf++) {
            float mb0 = Ms[kb + nf * 8 + 2 * tig];
            float mb1 = Ms[kb + nf * 8 + 2 * tig + 1];
            #pragma unroll
            for (int mf = 0; mf < 2; mf++) {
                sacc[mf][nf][0] += mb0; sacc[mf][nf][1] += mb1;
                sacc[mf][nf][2] += mb0; sacc[mf][nf][3] += mb1;
            }
        }

        #pragma unroll
        for (int rs = 0; rs < 4; rs++) {
            int mf = rs >> 1, cp = rs & 1;
            float lmax = -1e30f;
            #pragma unroll
            for (int nf = 0; nf < 4; nf++)
                lmax = fmaxf(lmax, fmaxf(sacc[mf][nf][2 * cp], sacc[mf][nf][2 * cp + 1]));
            lmax = fmaxf(lmax, __shfl_xor_sync(0xffffffffu, lmax, 1));
            lmax = fmaxf(lmax, __shfl_xor_sync(0xffffffffu, lmax, 2));
            float mnew = fmaxf(mrun[rs], lmax);
            float corr = __expf(mrun[rs] - mnew);
            float psum = 0.f;
            int prow = mf * 16 + gid + cp * 8;
            #pragma unroll
            for (int nf = 0; nf < 4; nf++) {
                uint32_t u0 = f2tf32(__expf(sacc[mf][nf][2 * cp] - mnew));
                uint32_t u1 = f2tf32(__expf(sacc[mf][nf][2 * cp + 1] - mnew));
                psum += __uint_as_float(u0) + __uint_as_float(u1);
                Pw[prow * PST + nf * 8 + 2 * tig] = u0;
                Pw[prow * PST + nf * 8 + 2 * tig + 1] = u1;
            }
            psum += __shfl_xor_sync(0xffffffffu, psum, 1);
            psum += __shfl_xor_sync(0xffffffffu, psum, 2);
            lrun[rs] = lrun[rs] * corr + psum;
            mrun[rs] = mnew;
            #pragma unroll
            for (int nf2 = 0; nf2 < 8; nf2++) {
                O[mf][nf2][2 * cp] *= corr;
                O[mf][nf2][2 * cp + 1] *= corr;
            }
        }
        __syncwarp();

        #pragma unroll
        for (int ks2 = 0; ks2 < 4; ks2++) {
            int k0 = ks2 * 8;
            uint32_t ap[2][4];
            #pragma unroll
            for (int mf = 0; mf < 2; mf++) {
                int r = mf * 16 + gid;
                ap[mf][0] = Pw[r * PST + k0 + tig];
                ap[mf][1] = Pw[(r + 8) * PST + k0 + tig];
                ap[mf][2] = Pw[r * PST + k0 + tig + 4];
                ap[mf][3] = Pw[(r + 8) * PST + k0 + tig + 4];
            }
            #pragma unroll
            for (int nf2 = 0; nf2 < 8; nf2++) {
                uint32_t bv0 = Vs[(kb + k0 + tig) * VST + nf2 * 8 + gid];
                uint32_t bv1 = Vs[(kb + k0 + tig + 4) * VST + nf2 * 8 + gid];
                mma_tf32_16x8x8(O[0][nf2], ap[0][0], ap[0][1], ap[0][2], ap[0][3],
                                bv0, bv1);
                mma_tf32_16x8x8(O[1][nf2], ap[1][0], ap[1][1], ap[1][2], ap[1][3],
                                bv0, bv1);
            }
        }
        __syncwarp();
    }

    float inv[4];
    #pragma unroll
    for (int rs = 0; rs < 4; rs++) inv[rs] = 1.0f / lrun[rs];
    #pragma unroll
    for (int mf = 0; mf < 2; mf++) {
        #pragma unroll
        for (int cp = 0; cp < 2; cp++) {
            int row = b * SEQ + qbase + mf * 16 + gid + cp * 8;
            float* orow = out + (size_t)row * HID + h * HDIM;
            float iv = inv[mf * 2 + cp];
            #pragma unroll
            for (int nf2 = 0; nf2 < 8; nf2++) {
                float2 v;
                v.x = tf32r(O[mf][nf2][2 * cp] * iv);
                v.y = tf32r(O[mf][nf2][2 * cp + 1] * iv);
                *reinterpret_cast<float2*>(orow + nf2 * 8 + 2 * tig) = v;
            }
        }
    }
}

// ---------------------------------------------------------------------------
// Warp-per-row LayerNorms: write fp32 x AND tf32-rounded xr
// ---------------------------------------------------------------------------
__device__ __forceinline__ void warp_ln_stats(const float* v, float& mean, float& inv)
{
    float s = 0.f, sq = 0.f;
    #pragma unroll
    for (int j = 0; j < 24; j++) { s += v[j]; sq += v[j] * v[j]; }
    #pragma unroll
    for (int o = 16; o > 0; o >>= 1) {
        s  += __shfl_xor_sync(0xffffffffu, s, o);
        sq += __shfl_xor_sync(0xffffffffu, sq, o);
    }
    mean = s * (1.0f / HID);
    float var = sq * (1.0f / HID) - mean * mean;
    inv = rsqrtf(var + 1e-12f);
}

__device__ __forceinline__ void warp_ln_write2(
    float* dst, float* dstr, const float* v, const float* lns, const float* lnb,
    int lane, float mean, float inv)
{
    #pragma unroll
    for (int i = 0; i < 6; i++) {
        int c = i * 128 + lane * 4;
        float4 g = *reinterpret_cast<const float4*>(lns + c);
        float4 bq = *reinterpret_cast<const float4*>(lnb + c);
        float4 o;
        o.x = (v[i * 4 + 0] - mean) * inv * g.x + bq.x;
        o.y = (v[i * 4 + 1] - mean) * inv * g.y + bq.y;
        o.z = (v[i * 4 + 2] - mean) * inv * g.z + bq.z;
        o.w = (v[i * 4 + 3] - mean) * inv * g.w + bq.w;
        *reinterpret_cast<float4*>(dst + c) = o;
        float4 r;
        r.x = tf32r(o.x); r.y = tf32r(o.y); r.z = tf32r(o.z); r.w = tf32r(o.w);
        *reinterpret_cast<float4*>(dstr + c) = r;
    }
}

__global__ __launch_bounds__(256) void embed_ln_kernel(
    const int* __restrict__ ids, const float* __restrict__ wemb,
    const float* __restrict__ pemb, const float* __restrict__ lns,
    const float* __restrict__ lnb, float* __restrict__ xout,
    float* __restrict__ xrout)
{
    int wid = threadIdx.x >> 5, lane = threadIdx.x & 31;
    int row = blockIdx.x * 8 + wid;
    int spos = row & (SEQ - 1);
    int id = ids[row];
    const float* wr = wemb + (size_t)id * HID;
    const float* pr = pemb + (size_t)spos * HID;
    float v[24];
    #pragma unroll
    for (int i = 0; i < 6; i++) {
        int c = i * 128 + lane * 4;
        float4 a = *reinterpret_cast<const float4*>(wr + c);
        float4 p = *reinterpret_cast<const float4*>(pr + c);
        v[i * 4 + 0] = a.x + p.x; v[i * 4 + 1] = a.y + p.y;
        v[i * 4 + 2] = a.z + p.z; v[i * 4 + 3] = a.w + p.w;
    }
    float mean, inv;
    warp_ln_stats(v, mean, inv);
    warp_ln_write2(xout + (size_t)row * HID, xrout + (size_t)row * HID,
                   v, lns, lnb, lane, mean, inv);
}

__global__ __launch_bounds__(256) void resid_ln_kernel(
    float* __restrict__ x, const float* __restrict__ y,
    float* __restrict__ xr,
    const float* __restrict__ lns, const float* __restrict__ lnb)
{
    int wid = threadIdx.x >> 5, lane = threadIdx.x & 31;
    int row = blockIdx.x * 8 + wid;
    float* xrow = x + (size_t)row * HID;
    const float* yr = y + (size_t)row * HID;
    float v[24];
    #pragma unroll
    for (int i = 0; i < 6; i++) {
        int c = i * 128 + lane * 4;
        float4 a = *reinterpret_cast<const float4*>(xrow + c);
        float4 bq = *reinterpret_cast<const float4*>(yr + c);
        v[i * 4 + 0] = a.x + bq.x; v[i * 4 + 1] = a.y + bq.y;
        v[i * 4 + 2] = a.z + bq.z; v[i * 4 + 3] = a.w + bq.w;
    }
    float mean, inv;
    warp_ln_stats(v, mean, inv);
    warp_ln_write2(xrow, xr + (size_t)row * HID, v, lns, lnb, lane, mean, inv);
}

// ---------------------------------------------------------------------------
// Classifier: warp per row (fp32 exact)
// ---------------------------------------------------------------------------
__global__ __launch_bounds__(256) void cls_kernel(
    const float* __restrict__ x, const float* __restrict__ W,
    const float* __restrict__ bias, float* __restrict__ out)
{
    int wid = threadIdx.x >> 5, lane = threadIdx.x & 31;
    int row = blockIdx.x * 8 + wid;
    const float* xr = x + (size_t)row * HID;
    float acc[NTAGS];
    #pragma unroll
    for (int n = 0; n < NTAGS; n++) acc[n] = 0.f;
    #pragma unroll
    for (int i = 0; i < 24; i++) {
        int k = i * 32 + lane;
        float xv = xr[k];
        const float* wr = W + k * NTAGS;
        #pragma unroll
        for (int n = 0; n < NTAGS; n++) acc[n] += xv * wr[n];
    }
    #pragma unroll
    for (int n = 0; n < NTAGS; n++) {
        #pragma unroll
        for (int o = 16; o > 0; o >>= 1)
            acc[n] += __shfl_xor_sync(0xffffffffu, acc[n], o);
    }
    if (lane < NTAGS)
        out[(size_t)row * NTAGS + lane] = acc[lane] + bias[lane];
}

// ---------------------------------------------------------------------------
// CRF: one warp per batch element
// ---------------------------------------------------------------------------
__global__ __launch_bounds__(32) void crf_kernel(
    const float* __restrict__ logits, const int* __restrict__ labels,
    const float* __restrict__ cstart, const float* __restrict__ cend,
    const float* __restrict__ ctrans, float* __restrict__ nmd)
{
    int b = blockIdx.x;
    int lane = threadIdx.x;
    const float* lg = logits + (size_t)b * SEQ * NTAGS;
    const int* lab = labels + b * SEQ;

    float part = 0.f;
    int cnt = 0;
    for (int s = lane; s < SEQ; s += 32) {
        int lv = lab[s];
        bool mk = (s == 0) || (lv != -100);
        cnt += mk ? 1 : 0;
        if (s >= 1 && mk) {
            int lp = lab[s - 1]; int tp = (lp == -100) ? 0 : lp;
            int tc = (lv == -100) ? 0 : lv;
            part += ctrans[tp * NTAGS + tc] + lg[s * NTAGS + tc];
        }
    }
    #pragma unroll
    for (int o = 16; o > 0; o >>= 1) {
        part += __shfl_xor_sync(0xffffffffu, part, o);
        cnt  += __shfl_xor_sync(0xffffffffu, cnt, o);
    }

    int t = (lane < NTAGS) ? lane : 0;
    float tt[NTAGS];
    #pragma unroll
    for (int i = 0; i < NTAGS; i++) tt[i] = ctrans[i * NTAGS + t];
    float score = cstart[t] + lg[t];

    for (int s = 1; s < SEQ; s++) {
        float e = lg[s * NTAGS + t];
        float v[NTAGS];
        float vmax = -1e30f;
        #pragma unroll
        for (int i = 0; i < NTAGS; i++) {
            float si = __shfl_sync(0xffffffffu, score, i);
            v[i] = si + tt[i];
            vmax = fmaxf(vmax, v[i]);
        }
        float smv = 0.f;
        #pragma unroll
        for (int i = 0; i < NTAGS; i++) smv += __expf(v[i] - vmax);
        float nxt = vmax + __logf(smv) + e;
        bool mk = (lab[s] != -100);
        score = mk ? nxt : score;
    }

    float fin = score + cend[t];
    float gmax = -1e30f;
    #pragma unroll
    for (int i = 0; i < NTAGS; i++)
        gmax = fmaxf(gmax, __shfl_sync(0xffffffffu, fin, i));
    float gs = 0.f;
    #pragma unroll
    for (int i = 0; i < NTAGS; i++)
        gs += __expf(__shfl_sync(0xffffffffu, fin, i) - gmax);
    float denom = gmax + __logf(gs);

    if (lane == 0) {
        int l0 = lab[0]; int t0 = (l0 == -100) ? 0 : l0;
        int seq_end = cnt - 1;
        int le = lab[seq_end]; int te = (le == -100) ? 0 : le;
        float num = part + cstart[t0] + lg[t0] + cend[te];
        nmd[b] = num - denom;
    }
}

__global__ __launch_bounds__(32) void loss_kernel(
    const float* __restrict__ nmd, float* __restrict__ out)
{
    int lane = threadIdx.x;
    float v = (lane < BATCH) ? nmd[lane] : 0.f;
    #pragma unroll
    for (int o = 16; o > 0; o >>= 1) v += __shfl_xor_sync(0xffffffffu, v, o);
    if (lane == 0) out[0] = -(v * (1.0f / BATCH));
}

// ---------------------------------------------------------------------------
// Launcher
// ---------------------------------------------------------------------------
extern "C" void kernel_launch(void* const* d_in, const int* in_sizes, int n_in,
                              void* d_out, int out_size)
{
    const int*   input_ids = (const int*)d_in[0];
    const int*   amask     = (const int*)d_in[1];
    const int*   labels    = (const int*)d_in[2];
    const float* word_emb  = (const float*)d_in[3];
    const float* pos_emb   = (const float*)d_in[4];
    const float* eln_s     = (const float*)d_in[5];
    const float* eln_b     = (const float*)d_in[6];
    const float* Wqkv      = (const float*)d_in[7];
    const float* bqkv      = (const float*)d_in[8];
    const float* Wo        = (const float*)d_in[9];
    const float* bo        = (const float*)d_in[10];
    const float* ln1s      = (const float*)d_in[11];
    const float* ln1b      = (const float*)d_in[12];
    const float* Wff1      = (const float*)d_in[13];
    const float* bff1      = (const float*)d_in[14];
    const float* Wff2      = (const float*)d_in[15];
    const float* bff2      = (const float*)d_in[16];
    const float* ln2s      = (const float*)d_in[17];
    const float* ln2b      = (const float*)d_in[18];
    const float* Wcls      = (const float*)d_in[19];
    const float* bcls      = (const float*)d_in[20];
    const float* cstart    = (const float*)d_in[21];
    const float* cend      = (const float*)d_in[22];
    const float* ctrans    = (const float*)d_in[23];
    float* out = (float*)d_out;

    float *x, *xr, *qkv, *attn, *ffn, *tmp, *nmd, *w;
    cudaGetSymbolAddress((void**)&x,    g_x);
    cudaGetSymbolAddress((void**)&xr,   g_xr);
    cudaGetSymbolAddress((void**)&qkv,  g_qkv);
    cudaGetSymbolAddress((void**)&attn, g_attn);
    cudaGetSymbolAddress((void**)&ffn,  g_ffn);
    cudaGetSymbolAddress((void**)&tmp,  g_tmp);
    cudaGetSymbolAddress((void**)&nmd,  g_nmd);
    cudaGetSymbolAddress((void**)&w,    g_w);

    cudaFuncSetAttribute(gemm_tc_kernel,
        cudaFuncAttributeMaxDynamicSharedMemorySize, GEMM_DSMEM);
    cudaFuncSetAttribute(attn_kernel,
        cudaFuncAttributeMaxDynamicSharedMemorySize, ATN_SMEM);

    conv_tf32_kernel<<<1184, 256>>>(Wqkv, Wo, Wff1, Wff2, w);

    embed_ln_kernel<<<NTOK / 8, 256>>>(input_ids, word_emb, pos_emb,
                                       eln_s, eln_b, x, xr);

    for (int L = 0; L < NLAYER; L++) {
        // QKV: A = xr (rounded), out rounded (feeds attention raw-bit)
        gemm_tc_kernel<<<dim3(3 * HID / 128, NTOK / 128), 256, GEMM_DSMEM>>>(
            xr, w + W_QKV_OFF + (size_t)L * HID * 3 * HID,
            bqkv + (size_t)L * 3 * HID, qkv, NTOK, 3 * HID, HID, 2);

        attn_kernel<<<BATCH * NHEAD, 256, ATN_SMEM>>>(qkv, amask, attn);

        // WO: A = attn (rounded), out fp32 (feeds LN)
        gemm_tc_kernel<<<dim3(HID / 128, NTOK / 128), 256, GEMM_DSMEM>>>(
            attn, w + W_WO_OFF + (size_t)L * HID * HID,
            bo + (size_t)L * HID, tmp, NTOK, HID, HID, 0);

        resid_ln_kernel<<<NTOK / 8, 256>>>(x, tmp, xr,
            ln1s + (size_t)L * HID, ln1b + (size_t)L * HID);

        // FF1: A = xr, gelu + round (feeds FF2 raw-bit)
        gemm_tc_kernel<<<dim3(FFN / 128, NTOK / 128), 256, GEMM_DSMEM>>>(
            xr, w + W_FF1_OFF + (size_t)L * HID * FFN,
            bff1 + (size_t)L * FFN, ffn, NTOK, FFN, HID, 3);

        // FF2: A = ffn (rounded), out fp32 (feeds LN)
        gemm_tc_kernel<<<dim3(HID / 128, NTOK / 128), 256, GEMM_DSMEM>>>(
            ffn, w + W_FF2_OFF + (size_t)L * FFN * HID,
            bff2 + (size_t)L * HID, tmp, NTOK, HID, FFN, 0);

        resid_ln_kernel<<<NTOK / 8, 256>>>(x, tmp, xr,
            ln2s + (size_t)L * HID, ln2b + (size_t)L * HID);
    }

    cls_kernel<<<NTOK / 8, 256>>>(x, Wcls, bcls, out + 1);
    crf_kernel<<<BATCH, 32>>>(out + 1, labels, cstart, cend, ctrans, nmd);
    loss_kernel<<<1, 32>>>(nmd, out);
}

// round 10
// speedup vs baseline: 1.5438x; 1.4037x over previous
#include <cuda_runtime.h>
#include <cuda_fp16.h>
#include <math.h>
#include <stdint.h>

// ---------------------------------------------------------------------------
// Problem constants
// ---------------------------------------------------------------------------
#define BATCH 16
#define SEQ 256
#define NTOK (BATCH * SEQ)          // 4096
#define HID 768
#define NHEAD 12
#define HDIM 64
#define FFN 3072
#define NLAYER 6
#define NTAGS 9

// Weight scratch offsets (in half elements; identical numeric layout as fp32 version)
#define W_QKV_OFF 0
#define W_QKV_SZ  (NLAYER * HID * 3 * HID)
#define W_WO_OFF  (W_QKV_OFF + W_QKV_SZ)
#define W_WO_SZ   (NLAYER * HID * HID)
#define W_FF1_OFF (W_WO_OFF + W_WO_SZ)
#define W_FF1_SZ  (NLAYER * HID * FFN)
#define W_FF2_OFF (W_FF1_OFF + W_FF1_SZ)
#define W_FF2_SZ  (NLAYER * FFN * HID)
#define W_TOTAL   (W_FF2_OFF + W_FF2_SZ)

// ---------------------------------------------------------------------------
// Scratch (device globals; no allocation allowed)
// ---------------------------------------------------------------------------
__device__ float  g_x[NTOK * HID];        // residual stream (fp32 exact)
__device__ __half g_xr[NTOK * HID];       // half copy of x (GEMM A input)
__device__ __half g_qkv[NTOK * 3 * HID];  // half (QKV epilogue)
__device__ __half g_attn[NTOK * HID];     // half (attn epilogue)
__device__ __half g_ffn[NTOK * FFN];      // half (FF1 epilogue)
__device__ float  g_tmp[NTOK * HID];      // fp32 (WO/FF2 outputs -> LN)
__device__ float  g_nmd[BATCH];
__device__ __half g_w[W_TOTAL];           // half weights, k-pair interleaved [K/2][N] pairs

// ---------------------------------------------------------------------------
// helpers
// ---------------------------------------------------------------------------
__device__ __forceinline__ uint32_t smem_u32(const void* p) {
    uint32_t a;
    asm("{ .reg .u64 t; cvta.to.shared.u64 t, %1; cvt.u32.u64 %0, t; }"
        : "=r"(a) : "l"(p));
    return a;
}

__device__ __forceinline__ void mma_f16_16x8x16(
    float* c, uint32_t a0, uint32_t a1, uint32_t a2, uint32_t a3,
    uint32_t b0, uint32_t b1)
{
    asm volatile(
        "mma.sync.aligned.m16n8k16.row.col.f32.f16.f16.f32 "
        "{%0,%1,%2,%3}, {%4,%5,%6,%7}, {%8,%9}, {%0,%1,%2,%3};"
        : "+f"(c[0]), "+f"(c[1]), "+f"(c[2]), "+f"(c[3])
        : "r"(a0), "r"(a1), "r"(a2), "r"(a3), "r"(b0), "r"(b1));
}

__device__ __forceinline__ float gelu_tanh(float v) {
    float c = 0.7978845608028654f;
    float u = c * (v + 0.044715f * v * v * v);
    return 0.5f * v * (1.0f + tanhf(u));
}

__device__ __forceinline__ uint32_t pack2(float x, float y) {
    __half2 h = __floats2half2_rn(x, y);
    return *reinterpret_cast<uint32_t*>(&h);
}

#define CP_ASYNC16(dst, src) \
    asm volatile("cp.async.cg.shared.global [%0], [%1], 16;" \
        :: "r"(dst), "l"(src) : "memory")
#define CP_COMMIT() asm volatile("cp.async.commit_group;" ::: "memory")
#define CP_WAIT2()  asm volatile("cp.async.wait_group 2;" ::: "memory")

// ---------------------------------------------------------------------------
// Weight pack: fp32 [rows][N] -> half2 k-pair interleaved [rows/2][N]
// pair word at (kp, n) = (W[2kp][n] low, W[2kp+1][n] high)
// ---------------------------------------------------------------------------
__device__ __forceinline__ void pack_group(
    const float* __restrict__ src, __half2* __restrict__ dst,
    int rows2, int N, int t0, int stride)
{
    int nq = N >> 2;
    int total = rows2 * nq;
    for (int i = t0; i < total; i += stride) {
        int kp = i / nq, ns = (i - kp * nq) * 4;
        float4 a = *reinterpret_cast<const float4*>(src + (size_t)(2 * kp) * N + ns);
        float4 b = *reinterpret_cast<const float4*>(src + (size_t)(2 * kp + 1) * N + ns);
        uint4 u;
        u.x = pack2(a.x, b.x);
        u.y = pack2(a.y, b.y);
        u.z = pack2(a.z, b.z);
        u.w = pack2(a.w, b.w);
        *reinterpret_cast<uint4*>(dst + (size_t)kp * N + ns) = u;
    }
}

__global__ __launch_bounds__(256) void conv_pack_kernel(
    const float* __restrict__ s0, const float* __restrict__ s1,
    const float* __restrict__ s2, const float* __restrict__ s3,
    __half* __restrict__ w)
{
    int t0 = blockIdx.x * blockDim.x + threadIdx.x;
    int stride = gridDim.x * blockDim.x;
    pack_group(s0, (__half2*)(w + W_QKV_OFF), NLAYER * HID / 2,  3 * HID, t0, stride);
    pack_group(s1, (__half2*)(w + W_WO_OFF),  NLAYER * HID / 2,  HID,     t0, stride);
    pack_group(s2, (__half2*)(w + W_FF1_OFF), NLAYER * HID / 2,  FFN,     t0, stride);
    pack_group(s3, (__half2*)(w + W_FF2_OFF), NLAYER * FFN / 2,  HID,     t0, stride);
}

// ---------------------------------------------------------------------------
// fp16 tensor-core GEMM (m16n8k16), 3-stage cp.async, 2 CTAs/SM.
// A: half row-major [M][K]. B2: half2 pairs [K/2][N]. C: half or float.
// act bit0 = gelu, bit1 = half output.
// ---------------------------------------------------------------------------
#define AST2 20                  // half2 words per A row (16 + 4 pad)
#define BST2 132                 // half2 words per B row (128 + 4 pad)
#define A_STG (128 * AST2)
#define B_STG (16 * BST2)
#define GEMM_DSMEM ((3 * A_STG + 3 * B_STG) * 4)

__global__ __launch_bounds__(256, 2) void gemm_tc_kernel(
    const __half* __restrict__ A, const __half2* __restrict__ B2,
    const float* __restrict__ bias, void* __restrict__ Cout,
    int M, int N, int K, int act)
{
    extern __shared__ uint32_t gsm[];
    uint32_t* AsB = gsm;               // [3][128][AST2]
    uint32_t* BsB = gsm + 3 * A_STG;   // [3][16][BST2]
    const uint32_t s_as = smem_u32(AsB);
    const uint32_t s_bs = smem_u32(BsB);

    const int tid = threadIdx.x;
    const int wid = tid >> 5;
    const int lane = tid & 31;
    const int gid = lane >> 2;
    const int tig = lane & 3;
    const int moff = (wid >> 2) * 64;
    const int noff = (wid & 3) * 32;

    const int m0 = blockIdx.y * 128;
    const int n0 = blockIdx.x * 128;

    float acc[4][4][4];
    #pragma unroll
    for (int i = 0; i < 4; i++)
        #pragma unroll
        for (int j = 0; j < 4; j++)
            #pragma unroll
            for (int q = 0; q < 4; q++) acc[i][j][q] = 0.f;

    const int nch = K >> 5;

    auto issue = [&](int stage, int kc) {
        // A: 128 rows x 32 halves (64B/row) -> 2 x 16B per thread
        #pragma unroll
        for (int i = 0; i < 2; i++) {
            int r = i * 64 + (tid >> 2);
            int seg = tid & 3;
            uint32_t d = s_as + (uint32_t)(stage * A_STG + r * AST2 + seg * 4) * 4u;
            const __half* s = A + (size_t)(m0 + r) * K + kc + seg * 8;
            CP_ASYNC16(d, s);
        }
        // B: 16 pair-rows x 128 half2 (512B/row) -> 2 x 16B per thread
        #pragma unroll
        for (int i = 0; i < 2; i++) {
            int r = i * 8 + (tid >> 5);
            int seg = tid & 31;
            uint32_t d = s_bs + (uint32_t)(stage * B_STG + r * BST2 + seg * 4) * 4u;
            const __half2* s = B2 + (size_t)((kc >> 1) + r) * N + n0 + seg * 4;
            CP_ASYNC16(d, s);
        }
        CP_COMMIT();
    };

    issue(0, 0);
    issue(1, 32);

    #pragma unroll 1
    for (int c = 0; c < nch; c++) {
        if (c + 2 < nch) issue((c + 2) % 3, (c + 2) * 32);
        else CP_COMMIT();
        CP_WAIT2();
        __syncthreads();

        const uint32_t* Asb = AsB + (c % 3) * A_STG;
        const uint32_t* Bsb = BsB + (c % 3) * B_STG;

        #pragma unroll
        for (int ks = 0; ks < 2; ks++) {       // two k16 steps per 32-K chunk
            int k2 = ks * 8;                   // pair-index base
            uint32_t a[2][4], a2[2][4];
            #pragma unroll
            for (int mf = 0; mf < 2; mf++) {
                int r = moff + mf * 16 + gid;
                a[mf][0] = Asb[r * AST2 + k2 + tig];
                a[mf][1] = Asb[(r + 8) * AST2 + k2 + tig];
                a[mf][2] = Asb[r * AST2 + k2 + tig + 4];
                a[mf][3] = Asb[(r + 8) * AST2 + k2 + tig + 4];
            }
            #pragma unroll
            for (int mf = 0; mf < 2; mf++) {
                int r = moff + 32 + mf * 16 + gid;
                a2[mf][0] = Asb[r * AST2 + k2 + tig];
                a2[mf][1] = Asb[(r + 8) * AST2 + k2 + tig];
                a2[mf][2] = Asb[r * AST2 + k2 + tig + 4];
                a2[mf][3] = Asb[(r + 8) * AST2 + k2 + tig + 4];
            }
            uint32_t b[4][2];
            #pragma unroll
            for (int nf = 0; nf < 4; nf++) {
                int nc = noff + nf * 8 + gid;
                b[nf][0] = Bsb[(k2 + tig) * BST2 + nc];
                b[nf][1] = Bsb[(k2 + tig + 4) * BST2 + nc];
            }
            #pragma unroll
            for (int nf = 0; nf < 4; nf++) {
                mma_f16_16x8x16(acc[0][nf], a[0][0], a[0][1], a[0][2], a[0][3],
                                b[nf][0], b[nf][1]);
                mma_f16_16x8x16(acc[1][nf], a[1][0], a[1][1], a[1][2], a[1][3],
                                b[nf][0], b[nf][1]);
                mma_f16_16x8x16(acc[2][nf], a2[0][0], a2[0][1], a2[0][2], a2[0][3],
                                b[nf][0], b[nf][1]);
                mma_f16_16x8x16(acc[3][nf], a2[1][0], a2[1][1], a2[1][2], a2[1][3],
                                b[nf][0], b[nf][1]);
            }
        }
        __syncthreads();
    }

    // epilogue
    #pragma unroll
    for (int mf = 0; mf < 4; mf++) {
        #pragma unroll
        for (int half_ = 0; half_ < 2; half_++) {
            int row = m0 + moff + mf * 16 + gid + half_ * 8;
            const float* brow_ = bias + n0 + noff;
            #pragma unroll
            for (int nf = 0; nf < 4; nf++) {
                int cl = nf * 8 + 2 * tig;
                float vx = acc[mf][nf][half_ * 2 + 0] + brow_[cl];
                float vy = acc[mf][nf][half_ * 2 + 1] + brow_[cl + 1];
                if (act & 1) { vx = gelu_tanh(vx); vy = gelu_tanh(vy); }
                if (act & 2) {
                    __half* crow = (__half*)Cout + (size_t)row * N + n0 + noff;
                    *reinterpret_cast<uint32_t*>(crow + cl) = pack2(vx, vy);
                } else {
                    float* crow = (float*)Cout + (size_t)row * N + n0 + noff;
                    float2 v; v.x = vx; v.y = vy;
                    *reinterpret_cast<float2*>(crow + cl) = v;
                }
            }
        }
    }
}

// ---------------------------------------------------------------------------
// fp16 tensor-core flash attention. One block per (b,h); 8 warps x 32 q rows.
// ---------------------------------------------------------------------------
#define KTS2 264     // key stride for Kt2[32][264] (256 + 8 pad)
#define VST2 66      // d stride for Vs2[128][66]
#define PST2 20      // pair stride for Pw2[32][20]
#define ATN_U32 (32 * KTS2 + 128 * VST2 + 8 * 32 * PST2 + 256)
#define ATN_SMEM (ATN_U32 * 4)

__global__ __launch_bounds__(256) void attn_kernel(
    const __half* __restrict__ qkv, const int* __restrict__ amask,
    __half* __restrict__ out)
{
    extern __shared__ uint32_t ash[];
    uint32_t* Kt2 = ash;                     // [d_pair 32][key 256]
    uint32_t* Vs2 = ash + 32 * KTS2;         // [key_pair 128][d 64]
    uint32_t* Ps2 = Vs2 + 128 * VST2;        // [8 warps][row 32][key_pair 16]
    float* Ms = (float*)(Ps2 + 8 * 32 * PST2);

    const int bh = blockIdx.x;
    const int b = bh / NHEAD;
    const int h = bh % NHEAD;
    const int tid = threadIdx.x;
    const int wid = tid >> 5;
    const int lane = tid & 31;
    const int gid = lane >> 2;
    const int tig = lane & 3;

    const __half* base = qkv + (size_t)b * SEQ * (3 * HID);

    // stage K^T as d-pairs x keys
    {
        int key = tid;
        const __half2* kr = reinterpret_cast<const __half2*>(
            base + (size_t)key * (3 * HID) + HID + h * HDIM);
        #pragma unroll
        for (int d2 = 0; d2 < 32; d2++) {
            __half2 v = kr[d2];
            Kt2[d2 * KTS2 + key] = *reinterpret_cast<uint32_t*>(&v);
        }
        Ms[key] = (1.0f - (float)amask[b * SEQ + key]) * -1e9f;
    }
    // stage V as key-pairs x d
    {
        int kp = tid >> 1;
        int dh = (tid & 1) * 32;
        const __half* v0 = base + (size_t)(2 * kp) * (3 * HID) + 2 * HID + h * HDIM;
        const __half* v1 = v0 + (size_t)(3 * HID);
        #pragma unroll
        for (int d = 0; d < 32; d++) {
            __half2 p = __halves2half2(v0[dh + d], v1[dh + d]);
            Vs2[kp * VST2 + dh + d] = *reinterpret_cast<uint32_t*>(&p);
        }
    }

    // resident Q fragments, *0.125 (exact power of two)
    const int qbase = wid * 32;
    const __half2 scl = __float2half2_rn(0.125f);
    uint32_t aq[2][4][4];
    #pragma unroll
    for (int mf = 0; mf < 2; mf++) {
        const __half2* q0 = reinterpret_cast<const __half2*>(
            base + (size_t)(qbase + mf * 16 + gid) * (3 * HID) + h * HDIM);
        const __half2* q1 = q0 + (size_t)8 * (3 * HID) / 2;
        #pragma unroll
        for (int ks = 0; ks < 4; ks++) {
            __half2 t0 = __hmul2(q0[ks * 8 + tig], scl);
            __half2 t1 = __hmul2(q1[ks * 8 + tig], scl);
            __half2 t2 = __hmul2(q0[ks * 8 + tig + 4], scl);
            __half2 t3 = __hmul2(q1[ks * 8 + tig + 4], scl);
            aq[mf][ks][0] = *reinterpret_cast<uint32_t*>(&t0);
            aq[mf][ks][1] = *reinterpret_cast<uint32_t*>(&t1);
            aq[mf][ks][2] = *reinterpret_cast<uint32_t*>(&t2);
            aq[mf][ks][3] = *reinterpret_cast<uint32_t*>(&t3);
        }
    }
    __syncthreads();

    float mrun[4] = {-1e30f, -1e30f, -1e30f, -1e30f};
    float lrun[4] = {0.f, 0.f, 0.f, 0.f};
    float O[2][8][4];
    #pragma unroll
    for (int i = 0; i < 2; i++)
        #pragma unroll
        for (int j = 0; j < 8; j++)
            #pragma unroll
            for (int q = 0; q < 4; q++) O[i][j][q] = 0.f;

    uint32_t* Pw2 = Ps2 + wid * 32 * PST2;

    #pragma unroll 1
    for (int kc = 0; kc < 8; kc++) {
        const int kb = kc * 32;

        float sacc[2][4][4];
        #pragma unroll
        for (int i = 0; i < 2; i++)
            #pragma unroll
            for (int j = 0; j < 4; j++)
                #pragma unroll
                for (int q = 0; q < 4; q++) sacc[i][j][q] = 0.f;

        // S = Q @ K^T   (4 k16 steps over HDIM=64)
        #pragma unroll
        for (int ks = 0; ks < 4; ks++) {
            uint32_t bk[4][2];
            #pragma unroll
            for (int nf = 0; nf < 4; nf++) {
                bk[nf][0] = Kt2[(ks * 8 + tig) * KTS2 + kb + nf * 8 + gid];
                bk[nf][1] = Kt2[(ks * 8 + tig + 4) * KTS2 + kb + nf * 8 + gid];
            }
            #pragma unroll
            for (int mf = 0; mf < 2; mf++)
                #pragma unroll
                for (int nf = 0; nf < 4; nf++)
                    mma_f16_16x8x16(sacc[mf][nf],
                        aq[mf][ks][0], aq[mf][ks][1], aq[mf][ks][2], aq[mf][ks][3],
                        bk[nf][0], bk[nf][1]);
        }

        // mask bias
        #pragma unroll
        for (int nf = 0; nf < 4; nf++) {
            float mb0 = Ms[kb + nf * 8 + 2 * tig];
            float mb1 = Ms[kb + nf * 8 + 2 * tig + 1];
            #pragma unroll
            for (int mf = 0; mf < 2; mf++) {
                sacc[mf][nf][0] += mb0; sacc[mf][nf][1] += mb1;
                sacc[mf][nf][2] += mb0; sacc[mf][nf][3] += mb1;
            }
        }

        // online softmax; p stored as half2 pairs
        #pragma unroll
        for (int rs = 0; rs < 4; rs++) {
            int mf = rs >> 1, cp = rs & 1;
            float lmax = -1e30f;
            #pragma unroll
            for (int nf = 0; nf < 4; nf++)
                lmax = fmaxf(lmax, fmaxf(sacc[mf][nf][2 * cp], sacc[mf][nf][2 * cp + 1]));
            lmax = fmaxf(lmax, __shfl_xor_sync(0xffffffffu, lmax, 1));
            lmax = fmaxf(lmax, __shfl_xor_sync(0xffffffffu, lmax, 2));
            float mnew = fmaxf(mrun[rs], lmax);
            float corr = __expf(mrun[rs] - mnew);
            float psum = 0.f;
            int prow = mf * 16 + gid + cp * 8;
            #pragma unroll
            for (int nf = 0; nf < 4; nf++) {
                float p0 = __expf(sacc[mf][nf][2 * cp] - mnew);
                float p1 = __expf(sacc[mf][nf][2 * cp + 1] - mnew);
                __half2 ph = __floats2half2_rn(p0, p1);
                float2 pf = __half22float2(ph);
                psum += pf.x + pf.y;
                Pw2[prow * PST2 + nf * 4 + tig] = *reinterpret_cast<uint32_t*>(&ph);
            }
            psum += __shfl_xor_sync(0xffffffffu, psum, 1);
            psum += __shfl_xor_sync(0xffffffffu, psum, 2);
            lrun[rs] = lrun[rs] * corr + psum;
            mrun[rs] = mnew;
            #pragma unroll
            for (int nf2 = 0; nf2 < 8; nf2++) {
                O[mf][nf2][2 * cp] *= corr;
                O[mf][nf2][2 * cp + 1] *= corr;
            }
        }
        __syncwarp();

        // O += P @ V   (2 k16 steps over 32 keys)
        #pragma unroll
        for (int ks2 = 0; ks2 < 2; ks2++) {
            uint32_t ap[2][4];
            #pragma unroll
            for (int mf = 0; mf < 2; mf++) {
                int r = mf * 16 + gid;
                ap[mf][0] = Pw2[r * PST2 + ks2 * 8 + tig];
                ap[mf][1] = Pw2[(r + 8) * PST2 + ks2 * 8 + tig];
                ap[mf][2] = Pw2[r * PST2 + ks2 * 8 + tig + 4];
                ap[mf][3] = Pw2[(r + 8) * PST2 + ks2 * 8 + tig + 4];
            }
            #pragma unroll
            for (int nf2 = 0; nf2 < 8; nf2++) {
                uint32_t bv0 = Vs2[((kb >> 1) + ks2 * 8 + tig) * VST2 + nf2 * 8 + gid];
                uint32_t bv1 = Vs2[((kb >> 1) + ks2 * 8 + tig + 4) * VST2 + nf2 * 8 + gid];
                mma_f16_16x8x16(O[0][nf2], ap[0][0], ap[0][1], ap[0][2], ap[0][3],
                                bv0, bv1);
                mma_f16_16x8x16(O[1][nf2], ap[1][0], ap[1][1], ap[1][2], ap[1][3],
                                bv0, bv1);
            }
        }
        __syncwarp();
    }

    float inv[4];
    #pragma unroll
    for (int rs = 0; rs < 4; rs++) inv[rs] = 1.0f / lrun[rs];
    #pragma unroll
    for (int mf = 0; mf < 2; mf++) {
        #pragma unroll
        for (int cp = 0; cp < 2; cp++) {
            int row = b * SEQ + qbase + mf * 16 + gid + cp * 8;
            __half* orow = out + (size_t)row * HID + h * HDIM;
            float iv = inv[mf * 2 + cp];
            #pragma unroll
            for (int nf2 = 0; nf2 < 8; nf2++) {
                *reinterpret_cast<uint32_t*>(orow + nf2 * 8 + 2 * tig) =
                    pack2(O[mf][nf2][2 * cp] * iv, O[mf][nf2][2 * cp + 1] * iv);
            }
        }
    }
}

// ---------------------------------------------------------------------------
// Warp-per-row LayerNorms: write fp32 x AND half xr
// ---------------------------------------------------------------------------
__device__ __forceinline__ void warp_ln_stats(const float* v, float& mean, float& inv)
{
    float s = 0.f, sq = 0.f;
    #pragma unroll
    for (int j = 0; j < 24; j++) { s += v[j]; sq += v[j] * v[j]; }
    #pragma unroll
    for (int o = 16; o > 0; o >>= 1) {
        s  += __shfl_xor_sync(0xffffffffu, s, o);
        sq += __shfl_xor_sync(0xffffffffu, sq, o);
    }
    mean = s * (1.0f / HID);
    float var = sq * (1.0f / HID) - mean * mean;
    inv = rsqrtf(var + 1e-12f);
}

__device__ __forceinline__ void warp_ln_write2(
    float* dst, __half* dstr, const float* v, const float* lns, const float* lnb,
    int lane, float mean, float inv)
{
    #pragma unroll
    for (int i = 0; i < 6; i++) {
        int c = i * 128 + lane * 4;
        float4 g = *reinterpret_cast<const float4*>(lns + c);
        float4 bq = *reinterpret_cast<const float4*>(lnb + c);
        float4 o;
        o.x = (v[i * 4 + 0] - mean) * inv * g.x + bq.x;
        o.y = (v[i * 4 + 1] - mean) * inv * g.y + bq.y;
        o.z = (v[i * 4 + 2] - mean) * inv * g.z + bq.z;
        o.w = (v[i * 4 + 3] - mean) * inv * g.w + bq.w;
        *reinterpret_cast<float4*>(dst + c) = o;
        uint2 r;
        r.x = pack2(o.x, o.y);
        r.y = pack2(o.z, o.w);
        *reinterpret_cast<uint2*>(dstr + c) = r;
    }
}

__global__ __launch_bounds__(256) void embed_ln_kernel(
    const int* __restrict__ ids, const float* __restrict__ wemb,
    const float* __restrict__ pemb, const float* __restrict__ lns,
    const float* __restrict__ lnb, float* __restrict__ xout,
    __half* __restrict__ xrout)
{
    int wid = threadIdx.x >> 5, lane = threadIdx.x & 31;
    int row = blockIdx.x * 8 + wid;
    int spos = row & (SEQ - 1);
    int id = ids[row];
    const float* wr = wemb + (size_t)id * HID;
    const float* pr = pemb + (size_t)spos * HID;
    float v[24];
    #pragma unroll
    for (int i = 0; i < 6; i++) {
        int c = i * 128 + lane * 4;
        float4 a = *reinterpret_cast<const float4*>(wr + c);
        float4 p = *reinterpret_cast<const float4*>(pr + c);
        v[i * 4 + 0] = a.x + p.x; v[i * 4 + 1] = a.y + p.y;
        v[i * 4 + 2] = a.z + p.z; v[i * 4 + 3] = a.w + p.w;
    }
    float mean, inv;
    warp_ln_stats(v, mean, inv);
    warp_ln_write2(xout + (size_t)row * HID, xrout + (size_t)row * HID,
                   v, lns, lnb, lane, mean, inv);
}

__global__ __launch_bounds__(256) void resid_ln_kernel(
    float* __restrict__ x, const float* __restrict__ y,
    __half* __restrict__ xr,
    const float* __restrict__ lns, const float* __restrict__ lnb)
{
    int wid = threadIdx.x >> 5, lane = threadIdx.x & 31;
    int row = blockIdx.x * 8 + wid;
    float* xrow = x + (size_t)row * HID;
    const float* yr = y + (size_t)row * HID;
    float v[24];
    #pragma unroll
    for (int i = 0; i < 6; i++) {
        int c = i * 128 + lane * 4;
        float4 a = *reinterpret_cast<const float4*>(xrow + c);
        float4 bq = *reinterpret_cast<const float4*>(yr + c);
        v[i * 4 + 0] = a.x + bq.x; v[i * 4 + 1] = a.y + bq.y;
        v[i * 4 + 2] = a.z + bq.z; v[i * 4 + 3] = a.w + bq.w;
    }
    float mean, inv;
    warp_ln_stats(v, mean, inv);
    warp_ln_write2(xrow, xr + (size_t)row * HID, v, lns, lnb, lane, mean, inv);
}

// ---------------------------------------------------------------------------
// Classifier: warp per row (fp32 exact)
// ---------------------------------------------------------------------------
__global__ __launch_bounds__(256) void cls_kernel(
    const float* __restrict__ x, const float* __restrict__ W,
    const float* __restrict__ bias, float* __restrict__ out)
{
    int wid = threadIdx.x >> 5, lane = threadIdx.x & 31;
    int row = blockIdx.x * 8 + wid;
    const float* xr = x + (size_t)row * HID;
    float acc[NTAGS];
    #pragma unroll
    for (int n = 0; n < NTAGS; n++) acc[n] = 0.f;
    #pragma unroll
    for (int i = 0; i < 24; i++) {
        int k = i * 32 + lane;
        float xv = xr[k];
        const float* wr = W + k * NTAGS;
        #pragma unroll
        for (int n = 0; n < NTAGS; n++) acc[n] += xv * wr[n];
    }
    #pragma unroll
    for (int n = 0; n < NTAGS; n++) {
        #pragma unroll
        for (int o = 16; o > 0; o >>= 1)
            acc[n] += __shfl_xor_sync(0xffffffffu, acc[n], o);
    }
    if (lane < NTAGS)
        out[(size_t)row * NTAGS + lane] = acc[lane] + bias[lane];
}

// ---------------------------------------------------------------------------
// CRF: one warp per batch element
// ---------------------------------------------------------------------------
__global__ __launch_bounds__(32) void crf_kernel(
    const float* __restrict__ logits, const int* __restrict__ labels,
    const float* __restrict__ cstart, const float* __restrict__ cend,
    const float* __restrict__ ctrans, float* __restrict__ nmd)
{
    int b = blockIdx.x;
    int lane = threadIdx.x;
    const float* lg = logits + (size_t)b * SEQ * NTAGS;
    const int* lab = labels + b * SEQ;

    float part = 0.f;
    int cnt = 0;
    for (int s = lane; s < SEQ; s += 32) {
        int lv = lab[s];
        bool mk = (s == 0) || (lv != -100);
        cnt += mk ? 1 : 0;
        if (s >= 1 && mk) {
            int lp = lab[s - 1]; int tp = (lp == -100) ? 0 : lp;
            int tc = (lv == -100) ? 0 : lv;
            part += ctrans[tp * NTAGS + tc] + lg[s * NTAGS + tc];
        }
    }
    #pragma unroll
    for (int o = 16; o > 0; o >>= 1) {
        part += __shfl_xor_sync(0xffffffffu, part, o);
        cnt  += __shfl_xor_sync(0xffffffffu, cnt, o);
    }

    int t = (lane < NTAGS) ? lane : 0;
    float tt[NTAGS];
    #pragma unroll
    for (int i = 0; i < NTAGS; i++) tt[i] = ctrans[i * NTAGS + t];
    float score = cstart[t] + lg[t];

    for (int s = 1; s < SEQ; s++) {
        float e = lg[s * NTAGS + t];
        float v[NTAGS];
        float vmax = -1e30f;
        #pragma unroll
        for (int i = 0; i < NTAGS; i++) {
            float si = __shfl_sync(0xffffffffu, score, i);
            v[i] = si + tt[i];
            vmax = fmaxf(vmax, v[i]);
        }
        float smv = 0.f;
        #pragma unroll
        for (int i = 0; i < NTAGS; i++) smv += __expf(v[i] - vmax);
        float nxt = vmax + __logf(smv) + e;
        bool mk = (lab[s] != -100);
        score = mk ? nxt : score;
    }

    float fin = score + cend[t];
    float gmax = -1e30f;
    #pragma unroll
    for (int i = 0; i < NTAGS; i++)
        gmax = fmaxf(gmax, __shfl_sync(0xffffffffu, fin, i));
    float gs = 0.f;
    #pragma unroll
    for (int i = 0; i < NTAGS; i++)
        gs += __expf(__shfl_sync(0xffffffffu, fin, i) - gmax);
    float denom = gmax + __logf(gs);

    if (lane == 0) {
        int l0 = lab[0]; int t0 = (l0 == -100) ? 0 : l0;
        int seq_end = cnt - 1;
        int le = lab[seq_end]; int te = (le == -100) ? 0 : le;
        float num = part + cstart[t0] + lg[t0] + cend[te];
        nmd[b] = num - denom;
    }
}

__global__ __launch_bounds__(32) void loss_kernel(
    const float* __restrict__ nmd, float* __restrict__ out)
{
    int lane = threadIdx.x;
    float v = (lane < BATCH) ? nmd[lane] : 0.f;
    #pragma unroll
    for (int o = 16; o > 0; o >>= 1) v += __shfl_xor_sync(0xffffffffu, v, o);
    if (lane == 0) out[0] = -(v * (1.0f / BATCH));
}

// ---------------------------------------------------------------------------
// Launcher
// ---------------------------------------------------------------------------
extern "C" void kernel_launch(void* const* d_in, const int* in_sizes, int n_in,
                              void* d_out, int out_size)
{
    const int*   input_ids = (const int*)d_in[0];
    const int*   amask     = (const int*)d_in[1];
    const int*   labels    = (const int*)d_in[2];
    const float* word_emb  = (const float*)d_in[3];
    const float* pos_emb   = (const float*)d_in[4];
    const float* eln_s     = (const float*)d_in[5];
    const float* eln_b     = (const float*)d_in[6];
    const float* Wqkv      = (const float*)d_in[7];
    const float* bqkv      = (const float*)d_in[8];
    const float* Wo        = (const float*)d_in[9];
    const float* bo        = (const float*)d_in[10];
    const float* ln1s      = (const float*)d_in[11];
    const float* ln1b      = (const float*)d_in[12];
    const float* Wff1      = (const float*)d_in[13];
    const float* bff1      = (const float*)d_in[14];
    const float* Wff2      = (const float*)d_in[15];
    const float* bff2      = (const float*)d_in[16];
    const float* ln2s      = (const float*)d_in[17];
    const float* ln2b      = (const float*)d_in[18];
    const float* Wcls      = (const float*)d_in[19];
    const float* bcls      = (const float*)d_in[20];
    const float* cstart    = (const float*)d_in[21];
    const float* cend      = (const float*)d_in[22];
    const float* ctrans    = (const float*)d_in[23];
    float* out = (float*)d_out;

    float *x, *tmp, *nmd;
    __half *xr, *qkv, *attn, *ffn, *w;
    cudaGetSymbolAddress((void**)&x,    g_x);
    cudaGetSymbolAddress((void**)&xr,   g_xr);
    cudaGetSymbolAddress((void**)&qkv,  g_qkv);
    cudaGetSymbolAddress((void**)&attn, g_attn);
    cudaGetSymbolAddress((void**)&ffn,  g_ffn);
    cudaGetSymbolAddress((void**)&tmp,  g_tmp);
    cudaGetSymbolAddress((void**)&nmd,  g_nmd);
    cudaGetSymbolAddress((void**)&w,    g_w);

    cudaFuncSetAttribute(gemm_tc_kernel,
        cudaFuncAttributeMaxDynamicSharedMemorySize, GEMM_DSMEM);
    cudaFuncSetAttribute(attn_kernel,
        cudaFuncAttributeMaxDynamicSharedMemorySize, ATN_SMEM);

    conv_pack_kernel<<<1184, 256>>>(Wqkv, Wo, Wff1, Wff2, w);

    embed_ln_kernel<<<NTOK / 8, 256>>>(input_ids, word_emb, pos_emb,
                                       eln_s, eln_b, x, xr);

    for (int L = 0; L < NLAYER; L++) {
        // QKV: A = xr, half out (feeds attention)
        gemm_tc_kernel<<<dim3(3 * HID / 128, NTOK / 128), 256, GEMM_DSMEM>>>(
            xr, (const __half2*)(w + W_QKV_OFF + (size_t)L * HID * 3 * HID),
            bqkv + (size_t)L * 3 * HID, qkv, NTOK, 3 * HID, HID, 2);

        attn_kernel<<<BATCH * NHEAD, 256, ATN_SMEM>>>(qkv, amask, attn);

        // WO: A = attn (half), fp32 out (feeds LN)
        gemm_tc_kernel<<<dim3(HID / 128, NTOK / 128), 256, GEMM_DSMEM>>>(
            attn, (const __half2*)(w + W_WO_OFF + (size_t)L * HID * HID),
            bo + (size_t)L * HID, tmp, NTOK, HID, HID, 0);

        resid_ln_kernel<<<NTOK / 8, 256>>>(x, tmp, xr,
            ln1s + (size_t)L * HID, ln1b + (size_t)L * HID);

        // FF1: A = xr, gelu + half out
        gemm_tc_kernel<<<dim3(FFN / 128, NTOK / 128), 256, GEMM_DSMEM>>>(
            xr, (const __half2*)(w + W_FF1_OFF + (size_t)L * HID * FFN),
            bff1 + (size_t)L * FFN, ffn, NTOK, FFN, HID, 3);

        // FF2: A = ffn (half), fp32 out
        gemm_tc_kernel<<<dim3(HID / 128, NTOK / 128), 256, GEMM_DSMEM>>>(
            ffn, (const __half2*)(w + W_FF2_OFF + (size_t)L * FFN * HID),
            bff2 + (size_t)L * HID, tmp, NTOK, HID, FFN, 0);

        resid_ln_kernel<<<NTOK / 8, 256>>>(x, tmp, xr,
            ln2s + (size_t)L * HID, ln2b + (size_t)L * HID);
    }

    cls_kernel<<<NTOK / 8, 256>>>(x, Wcls, bcls, out + 1);
    crf_kernel<<<BATCH, 32>>>(out + 1, labels, cstart, cend, ctrans, nmd);
    loss_kernel<<<1, 32>>>(nmd, out);
}